// round 12
// baseline (speedup 1.0000x reference)
#include <cuda_runtime.h>
#include <cstddef>

// ===========================================================================
// WorldModel RSSM persistent kernel. R=16 x C=2 GEMM tiles with software-
// pipelined weight prefetch; zc weights streamed with evict-first.
// S=32 C=32 D=4096 H=1024 A=6 B=16 T=64 TOK=4096, out feats [16,64,5120]
// ===========================================================================

#define NBLK 148
#define TPB  1024
#define GPB  4                  // 256-thread groups per block
#define NG   (NBLK * GPB)       // 592 groups

#define CH_Q1 64                // prior layer1:  K=4096, Kc=64
#define CH_P1 128               // post  layer1:  K=8192, Kc=64
#define CH_L  64                // layers 2/3:    K=1024, Kc=16
#define CH_ZC 32                // z/cand:        K=5120, Kc=160

// ---------------------------------------------------------------------------
// Device scratch
// ---------------------------------------------------------------------------
__device__ float g_deter[16 * 4096];
__device__ float g_gx[16 * 1024];
__device__ float g_hqA[16 * 1024];
__device__ float g_hqB[16 * 1024];
__device__ float g_hpA[16 * 1024];
__device__ float g_hpB[16 * 1024];
__device__ float g_partQ[CH_L * 16 * 1024];        // 64 chunks max (q side)
__device__ float g_partP[CH_P1 * 16 * 1024];       // 128 chunks max (p side)
__device__ float g_partZ[CH_ZC * 16 * 4096];
__device__ float g_partC[CH_ZC * 16 * 4096];
__device__ unsigned g_count;
__device__ unsigned g_gen;

// ---------------------------------------------------------------------------
__device__ __forceinline__ float2 ffma2(float2 a, float2 b, float2 c) {
    union U { float2 f; unsigned long long u; };
    U ua, ub, uc, ud;
    ua.f = a; ub.f = b; uc.f = c;
    asm("fma.rn.f32x2 %0, %1, %2, %3;"
        : "=l"(ud.u) : "l"(ua.u), "l"(ub.u), "l"(uc.u));
    return ud.f;
}

__device__ __forceinline__ void gbar() {
    __syncthreads();
    if (threadIdx.x == 0) {
        volatile unsigned* vg = &g_gen;
        unsigned gen = *vg;
        __threadfence();
        if (atomicAdd(&g_count, 1u) == NBLK - 1) {
            g_count = 0;
            __threadfence();
            *vg = gen + 1;
        } else {
            while (*vg == gen) { __nanosleep(32); }
        }
        __threadfence();
    }
    __syncthreads();
}

__device__ __forceinline__ float blockReduceSum(float v, float* sred) {
    int lane = threadIdx.x & 31, wid = threadIdx.x >> 5;
#pragma unroll
    for (int o = 16; o; o >>= 1) v += __shfl_xor_sync(0xffffffffu, v, o);
    __syncthreads();
    if (lane == 0) sred[wid] = v;
    __syncthreads();
    if (wid == 0) {
        float t = sred[lane];
#pragma unroll
        for (int o = 16; o; o >>= 1) t += __shfl_xor_sync(0xffffffffu, t, o);
        if (lane == 0) sred[0] = t;
    }
    __syncthreads();
    return sred[0];
}

struct InDesc { const float* A; int strideA; int offA; int KA; const float* B; };

// 16 rows x 2 cols of FMA for one k slice. sAk = &sA[kk*16].
__device__ __forceinline__ void fma16(const float* sAk, float2 w, float2* acc) {
    float2 wc0 = make_float2(w.x, w.x);
    float2 wc1 = make_float2(w.y, w.y);
    const float4* A4 = (const float4*)sAk;
#pragma unroll
    for (int j = 0; j < 4; j++) {
        float4 a = A4[j];
        float2 a01 = make_float2(a.x, a.y);
        float2 a23 = make_float2(a.z, a.w);
        acc[(2*j)*2 + 0]   = ffma2(a01, wc0, acc[(2*j)*2 + 0]);
        acc[(2*j)*2 + 1]   = ffma2(a01, wc1, acc[(2*j)*2 + 1]);
        acc[(2*j+1)*2 + 0] = ffma2(a23, wc0, acc[(2*j+1)*2 + 0]);
        acc[(2*j+1)*2 + 1] = ffma2(a23, wc1, acc[(2*j+1)*2 + 1]);
    }
}

// ---------------------------------------------------------------------------
// GEMM tile: ALL 16 rows x 512 cols (256 threads x 2 cols, LDG.64 weights).
// Full A chunk staged to smem; weight loads software-pipelined (dist 4).
// ---------------------------------------------------------------------------
template <bool STREAM>
__device__ __forceinline__ void gemm16(
    InDesc in, const float2* __restrict__ W2, int N2,
    int c2base, int k0, int Kc,
    float2* __restrict__ part2, int chunkIdx,
    float* sA, int gtid, int barId)
{
    // stage A[0..15][k0..k0+Kc) -> sA[k*16 + r]
    for (int idx = gtid; idx < 16 * Kc; idx += 256) {
        int k = idx >> 4, r = idx & 15;
        int gk = k0 + k;
        float v = (gk < in.KA) ? in.A[(size_t)r * in.strideA + in.offA + gk]
                               : in.B[(size_t)r * 4096 + (gk - in.KA)];
        sA[k * 16 + r] = v;
    }
    asm volatile("bar.sync %0, %1;" :: "r"(barId), "r"(256) : "memory");

    float2 acc[16];
#pragma unroll
    for (int i = 0; i < 16; i++) acc[i] = make_float2(0.f, 0.f);

    int col2 = c2base + gtid;
    const float2* Wp = W2 + (size_t)k0 * N2 + col2;

    float2 w[4];
#pragma unroll
    for (int j = 0; j < 4; j++)
        w[j] = STREAM ? __ldcs(Wp + (size_t)j * N2) : __ldg(Wp + (size_t)j * N2);
    Wp += (size_t)4 * N2;

    for (int kb = 0; kb + 4 < Kc; kb += 4) {
        float2 wn[4];
#pragma unroll
        for (int j = 0; j < 4; j++)
            wn[j] = STREAM ? __ldcs(Wp + (size_t)j * N2) : __ldg(Wp + (size_t)j * N2);
        Wp += (size_t)4 * N2;
#pragma unroll
        for (int j = 0; j < 4; j++) fma16(sA + (kb + j) * 16, w[j], acc);
#pragma unroll
        for (int j = 0; j < 4; j++) w[j] = wn[j];
    }
#pragma unroll
    for (int j = 0; j < 4; j++) fma16(sA + (Kc - 4 + j) * 16, w[j], acc);

    asm volatile("bar.sync %0, %1;" :: "r"(barId), "r"(256) : "memory");

#pragma unroll
    for (int rp = 0; rp < 8; rp++) {
        part2[(size_t)(chunkIdx * 16 + 2 * rp) * N2 + col2] =
            make_float2(acc[rp * 2 + 0].x, acc[rp * 2 + 1].x);
        part2[(size_t)(chunkIdx * 16 + 2 * rp + 1) * N2 + col2] =
            make_float2(acc[rp * 2 + 0].y, acc[rp * 2 + 1].y);
    }
}

// ---------------------------------------------------------------------------
// Phase: fused layer-1 GEMMs. q: deter@qW1 (K=4096, 128 tiles);
// p: [tok(tp),deter]@pW1 (K=8192, 256 tiles).
// ---------------------------------------------------------------------------
__device__ void phase_g1(bool doq, bool dop, int tp, const float* tokens,
                         const float2* qW1, const float2* pW1,
                         float* sMy, int gtid, int gid2, int barId)
{
    int qT = doq ? (2 * CH_Q1) : 0;
    int total = qT + (dop ? (2 * CH_P1) : 0);
    for (int t = gid2; t < total; t += NG) {
        if (t < qT) {
            int ch = t >> 1, ct = t & 1;
            InDesc in = { g_deter, 4096, 0, 4096, g_deter };
            gemm16<false>(in, qW1, 512, ct * 256, ch * 64, 64,
                          (float2*)g_partQ, ch, sMy, gtid, barId);
        } else {
            int u = t - qT;
            int ch = u >> 1, ct = u & 1;
            InDesc in = { tokens, 64 * 4096, tp * 4096, 4096, g_deter };
            gemm16<false>(in, pW1, 512, ct * 256, ch * 64, 64,
                          (float2*)g_partP, ch, sMy, gtid, barId);
        }
    }
}

// ---------------------------------------------------------------------------
// Phase: fused layer-2/3 GEMMs (K=1024, Kc=16, 128 tiles per side).
// ---------------------------------------------------------------------------
__device__ void phase_g23(bool doq, bool dop,
                          const float2* Wq, const float2* Wp,
                          const float* inq, const float* inp,
                          float* sMy, int gtid, int gid2, int barId)
{
    int qT = doq ? (2 * CH_L) : 0;
    int total = qT + (dop ? (2 * CH_L) : 0);
    for (int t = gid2; t < total; t += NG) {
        bool isq = t < qT;
        int u = isq ? t : (t - qT);
        int ch = u >> 1, ct = u & 1;
        InDesc in = { isq ? inq : inp, 1024, 0, 1024, isq ? inq : inp };
        gemm16<false>(in, isq ? Wq : Wp, 512, ct * 256, ch * 16, 16,
                      (float2*)(isq ? g_partQ : g_partP), ch, sMy, gtid, barId);
    }
}

// ---------------------------------------------------------------------------
// Phase: z/cand GEMM. in=[gx,deter] K=5120, N=4096 each. 512 tiles. Streamed.
// ---------------------------------------------------------------------------
__device__ void phase_zc(const float2* Wz, const float2* Wc,
                         float* sMy, int gtid, int gid2, int barId)
{
    const int total = 2 * 8 * CH_ZC;            // 512
    for (int t = gid2; t < total; t += NG) {
        bool isZ = t < 256;
        int u = t & 255;
        int ch = u >> 3, ct = u & 7;
        InDesc in = { g_gx, 1024, 0, 1024, g_deter };
        gemm16<true>(in, isZ ? Wz : Wc, 2048, ct * 256, ch * 160, 160,
                     (float2*)(isZ ? g_partZ : g_partC), ch, sMy, gtid, barId);
    }
}

// ---------------------------------------------------------------------------
// Phase: reduce partials + bias + LN + SiLU. Blocks 0..15 q, 16..31 p.
// ---------------------------------------------------------------------------
__device__ void phase_ln(bool doq, bool dop,
                         const float* qb, const float* qg, const float* qB,
                         const float* pb, const float* pg, const float* pB,
                         int chq, int chp, float* outq, float* outp,
                         float4* sLN, float* sred)
{
    int b = blockIdx.x;
    bool active = (b < 32);
    bool isq = b < 16;
    if (active && (isq ? !doq : !dop)) active = false;

    int s = threadIdx.x & 255, qd = threadIdx.x >> 8;
    float4 v = make_float4(0.f, 0.f, 0.f, 0.f);
    if (active) {
        int r = b & 15;
        const float4* part4 = (const float4*)(isq ? g_partQ : g_partP);
        int chunks = isq ? chq : chp;
        for (int ch = qd; ch < chunks; ch += 4) {
            float4 a = part4[(size_t)(ch * 16 + r) * 256 + s];
            v.x += a.x; v.y += a.y; v.z += a.z; v.w += a.w;
        }
    }
    sLN[qd * 256 + s] = v;
    __syncthreads();

    float4 tot = make_float4(0.f, 0.f, 0.f, 0.f);
    float partial = 0.f;
    if (active && qd == 0) {
        float4 a0 = sLN[s], a1 = sLN[256 + s], a2 = sLN[512 + s], a3 = sLN[768 + s];
        const float4* bias4 = (const float4*)(isq ? qb : pb);
        float4 bb = bias4[s];
        tot.x = a0.x + a1.x + a2.x + a3.x + bb.x;
        tot.y = a0.y + a1.y + a2.y + a3.y + bb.y;
        tot.z = a0.z + a1.z + a2.z + a3.z + bb.z;
        tot.w = a0.w + a1.w + a2.w + a3.w + bb.w;
        partial = tot.x + tot.y + tot.z + tot.w;
    }
    __syncthreads();                       // sLN reuse guard before reduce
    float mean = blockReduceSum(partial, sred) * (1.0f / 1024.0f);

    float4 d = make_float4(tot.x - mean, tot.y - mean, tot.z - mean, tot.w - mean);
    float sq = (active && qd == 0) ? (d.x*d.x + d.y*d.y + d.z*d.z + d.w*d.w) : 0.f;
    float var = blockReduceSum(sq, sred) * (1.0f / 1024.0f);

    if (active && qd == 0) {
        int r = b & 15;
        float rstd = rsqrtf(var + 1e-5f);
        const float4* g4 = (const float4*)(isq ? qg : pg);
        const float4* B4 = (const float4*)(isq ? qB : pB);
        float4 gg = g4[s], BB = B4[s], x;
        x.x = d.x * rstd * gg.x + BB.x;
        x.y = d.y * rstd * gg.y + BB.y;
        x.z = d.z * rstd * gg.z + BB.z;
        x.w = d.w * rstd * gg.w + BB.w;
        float4 o;
        o.x = x.x / (1.f + expf(-x.x));
        o.y = x.y / (1.f + expf(-x.y));
        o.z = x.z / (1.f + expf(-x.z));
        o.w = x.w / (1.f + expf(-x.w));
        ((float4*)(isq ? outq : outp))[r * 256 + s] = o;
    }
}

// ---------------------------------------------------------------------------
// Merged sample + GRU-input phase. Blocks 0..15: prior sample -> out.
// Blocks 16..31: posterior sample -> smem idx -> grux for step tp.
// ---------------------------------------------------------------------------
__device__ void phase_sample_grux(bool doq, bool dop, int t, int tp,
                                  const float* qbo, const float* pbo,
                                  const float* gprior, const float* gpost,
                                  const float* actions,
                                  const float* gW, const float* gb,
                                  const float* gg, const float* gB,
                                  int* sIdx, float* sAct, float* sred,
                                  float* out)
{
    int b = blockIdx.x;
    bool isq = b < 16;
    bool samp = (b < 32) && (isq ? doq : dop);
    bool grux = (b >= 16) && (b < 32) && dop;
    int r = b & 15;
    int s = threadIdx.x >> 5, lane = threadIdx.x & 31;

    if (grux && threadIdx.x < 6)
        sAct[threadIdx.x] = actions[((size_t)r * 64 + tp) * 6 + threadIdx.x];

    if (samp) {
        int col = s * 32 + lane;
        const float* part = isq ? g_partQ : g_partP;
        float logit = (isq ? qbo : pbo)[col];
#pragma unroll 8
        for (int ch = 0; ch < CH_L; ch++)
            logit += part[(size_t)(ch * 16 + r) * 1024 + col];

        float mx = logit;
#pragma unroll
        for (int o = 16; o; o >>= 1) mx = fmaxf(mx, __shfl_xor_sync(0xffffffffu, mx, o));
        float e = expf(logit - mx);
        float se = e;
#pragma unroll
        for (int o = 16; o; o >>= 1) se += __shfl_xor_sync(0xffffffffu, se, o);
        float p = 0.99f * (e / se) + (0.01f / 32.0f);

        int tt = isq ? t : tp;
        const float* gum = isq ? gprior : gpost;
        float score = logf(p) + gum[(size_t)((tt * 16 + r) * 32 + s) * 32 + lane];

        float bs = score; int bi = lane;
#pragma unroll
        for (int o = 16; o; o >>= 1) {
            float os = __shfl_xor_sync(0xffffffffu, bs, o);
            int   oi = __shfl_xor_sync(0xffffffffu, bi, o);
            if (os > bs || (os == bs && oi < bi)) { bs = os; bi = oi; }
        }
        if (isq) {
            out[((size_t)r * 64 + t) * 5120 + 4096 + col] = (lane == bi) ? 1.0f : 0.0f;
        } else if (lane == bi) {
            sIdx[s] = bi;
        }
    }
    __syncthreads();

    float v = 0.f;
    if (grux) {
        int col = threadIdx.x;
        v = gb[col];
#pragma unroll
        for (int s2 = 0; s2 < 32; s2++)
            v += gW[(size_t)(s2 * 32 + sIdx[s2]) * 1024 + col];
#pragma unroll
        for (int j = 0; j < 6; j++)
            v += sAct[j] * gW[(size_t)(1024 + j) * 1024 + col];
    }
    float mean = blockReduceSum(grux ? v : 0.f, sred) * (1.0f / 1024.0f);
    float d = v - mean;
    float var = blockReduceSum(grux ? d * d : 0.f, sred) * (1.0f / 1024.0f);
    if (grux) {
        float rstd = rsqrtf(var + 1e-5f);
        float x = d * rstd * gg[threadIdx.x] + gB[threadIdx.x];
        g_gx[r * 1024 + threadIdx.x] = x / (1.0f + expf(-x));
    }
}

// ---------------------------------------------------------------------------
// Phase: gate — reduce z/cand partials, update deter, write feats slice.
// ---------------------------------------------------------------------------
__device__ void phase_gate(int t, const float* gbz, const float* gbc,
                           float* out)
{
    int gt = blockIdx.x * TPB + threadIdx.x;
    int q8 = gt & 7, slot = gt >> 3;
    if (slot >= 16384) return;
    int b = slot >> 10, c4 = slot & 1023;

    const float4* pz4 = (const float4*)g_partZ;
    const float4* pc4 = (const float4*)g_partC;
    float4 zp = make_float4(0.f, 0.f, 0.f, 0.f);
    float4 cp = make_float4(0.f, 0.f, 0.f, 0.f);
#pragma unroll
    for (int ch = q8; ch < CH_ZC; ch += 8) {
        float4 a = pz4[(size_t)(ch * 16 + b) * 1024 + c4];
        float4 c = pc4[(size_t)(ch * 16 + b) * 1024 + c4];
        zp.x += a.x; zp.y += a.y; zp.z += a.z; zp.w += a.w;
        cp.x += c.x; cp.y += c.y; cp.z += c.z; cp.w += c.w;
    }
#pragma unroll
    for (int off = 4; off; off >>= 1) {
        zp.x += __shfl_down_sync(0xffffffffu, zp.x, off);
        zp.y += __shfl_down_sync(0xffffffffu, zp.y, off);
        zp.z += __shfl_down_sync(0xffffffffu, zp.z, off);
        zp.w += __shfl_down_sync(0xffffffffu, zp.w, off);
        cp.x += __shfl_down_sync(0xffffffffu, cp.x, off);
        cp.y += __shfl_down_sync(0xffffffffu, cp.y, off);
        cp.z += __shfl_down_sync(0xffffffffu, cp.z, off);
        cp.w += __shfl_down_sync(0xffffffffu, cp.w, off);
    }
    if (q8 == 0) {
        float4 bz = ((const float4*)gbz)[c4], bc = ((const float4*)gbc)[c4];
        zp.x += bz.x; zp.y += bz.y; zp.z += bz.z; zp.w += bz.w;
        cp.x += bc.x; cp.y += bc.y; cp.z += bc.z; cp.w += bc.w;
        float4* dt4 = (float4*)g_deter;
        float4 dv = dt4[b * 1024 + c4], dn;
        float z, cd;
        z = 1.f / (1.f + expf(-zp.x)); cd = tanhf(cp.x); dn.x = (1.f - z) * dv.x + z * cd;
        z = 1.f / (1.f + expf(-zp.y)); cd = tanhf(cp.y); dn.y = (1.f - z) * dv.y + z * cd;
        z = 1.f / (1.f + expf(-zp.z)); cd = tanhf(cp.z); dn.z = (1.f - z) * dv.z + z * cd;
        z = 1.f / (1.f + expf(-zp.w)); cd = tanhf(cp.w); dn.w = (1.f - z) * dv.w + z * cd;
        dt4[b * 1024 + c4] = dn;
        ((float4*)(out + ((size_t)b * 64 + t) * 5120))[c4] = dn;
    }
}

// ---------------------------------------------------------------------------
__global__ void __launch_bounds__(TPB, 1)
wm_kernel(const float* tokens, const float* actions,
          const float* gpost, const float* gprior,
          const float* pW1, const float* pb1, const float* pg1, const float* pB1,
          const float* pW2, const float* pb2, const float* pg2, const float* pB2,
          const float* pWo, const float* pbo,
          const float* qW1, const float* qb1, const float* qg1, const float* qB1,
          const float* qW2, const float* qb2, const float* qg2, const float* qB2,
          const float* qWo, const float* qbo,
          const float* gW, const float* gb, const float* gg, const float* gB,
          const float* gWz, const float* gbz, const float* gWc, const float* gbc,
          float* out)
{
    __shared__ float sStage[GPB * 2560];       // 4 groups x 10 KB A staging
    __shared__ float sRed[32];
    __shared__ int   sIdx[32];
    __shared__ float sAct[6];
    float4* sLN = (float4*)sStage;             // overlay: LN never overlaps GEMM

    int tid = threadIdx.x;
    int g = tid >> 8, gtid = tid & 255;
    int gid2 = g * NBLK + blockIdx.x;
    float* sMy = sStage + g * 2560;
    int barId = g + 1;

    const float2* pW1v = (const float2*)pW1; const float2* pW2v = (const float2*)pW2;
    const float2* pWov = (const float2*)pWo;
    const float2* qW1v = (const float2*)qW1; const float2* qW2v = (const float2*)qW2;
    const float2* qWov = (const float2*)qWo;
    const float2* gWzv = (const float2*)gWz; const float2* gWcv = (const float2*)gWc;

    {
        int i = blockIdx.x * TPB + tid;
        if (i < 16 * 4096) g_deter[i] = 0.0f;
    }
    gbar();

    // prologue: posterior(0) + grux(0)
    phase_g1(false, true, 0, tokens, qW1v, pW1v, sMy, gtid, gid2, barId);      gbar();
    phase_ln(false, true, qb1, qg1, qB1, pb1, pg1, pB1, CH_Q1, CH_P1,
             g_hqA, g_hpA, sLN, sRed);                                         gbar();
    phase_g23(false, true, qW2v, pW2v, g_hqA, g_hpA, sMy, gtid, gid2, barId);  gbar();
    phase_ln(false, true, qb2, qg2, qB2, pb2, pg2, pB2, CH_L, CH_L,
             g_hqB, g_hpB, sLN, sRed);                                         gbar();
    phase_g23(false, true, qWov, pWov, g_hqB, g_hpB, sMy, gtid, gid2, barId);  gbar();
    phase_sample_grux(false, true, 0, 0, qbo, pbo, gprior, gpost,
                      actions, gW, gb, gg, gB, sIdx, sAct, sRed, out);         gbar();

    for (int t = 0; t < 64; t++) {
        phase_zc(gWzv, gWcv, sMy, gtid, gid2, barId);                          gbar();
        phase_gate(t, gbz, gbc, out);                                          gbar();

        bool dop = (t < 63);
        phase_g1(true, dop, t + 1, tokens, qW1v, pW1v, sMy, gtid, gid2, barId); gbar();
        phase_ln(true, dop, qb1, qg1, qB1, pb1, pg1, pB1, CH_Q1, CH_P1,
                 g_hqA, g_hpA, sLN, sRed);                                      gbar();
        phase_g23(true, dop, qW2v, pW2v, g_hqA, g_hpA, sMy, gtid, gid2, barId); gbar();
        phase_ln(true, dop, qb2, qg2, qB2, pb2, pg2, pB2, CH_L, CH_L,
                 g_hqB, g_hpB, sLN, sRed);                                      gbar();
        phase_g23(true, dop, qWov, pWov, g_hqB, g_hpB, sMy, gtid, gid2, barId); gbar();
        phase_sample_grux(true, dop, t, t + 1, qbo, pbo, gprior, gpost,
                          actions, gW, gb, gg, gB, sIdx, sAct, sRed, out);      gbar();
    }
}

// ---------------------------------------------------------------------------
extern "C" void kernel_launch(void* const* d_in, const int* in_sizes, int n_in,
                              void* d_out, int out_size) {
    const float* tokens  = (const float*)d_in[0];
    const float* actions = (const float*)d_in[1];
    const float* gpost   = (const float*)d_in[2];
    const float* gprior  = (const float*)d_in[3];
    const float* pW1 = (const float*)d_in[4];  const float* pb1 = (const float*)d_in[5];
    const float* pg1 = (const float*)d_in[6];  const float* pB1 = (const float*)d_in[7];
    const float* pW2 = (const float*)d_in[8];  const float* pb2 = (const float*)d_in[9];
    const float* pg2 = (const float*)d_in[10]; const float* pB2 = (const float*)d_in[11];
    const float* pWo = (const float*)d_in[12]; const float* pbo = (const float*)d_in[13];
    const float* qW1 = (const float*)d_in[14]; const float* qb1 = (const float*)d_in[15];
    const float* qg1 = (const float*)d_in[16]; const float* qB1 = (const float*)d_in[17];
    const float* qW2 = (const float*)d_in[18]; const float* qb2 = (const float*)d_in[19];
    const float* qg2 = (const float*)d_in[20]; const float* qB2 = (const float*)d_in[21];
    const float* qWo = (const float*)d_in[22]; const float* qbo = (const float*)d_in[23];
    const float* gW  = (const float*)d_in[24]; const float* gb  = (const float*)d_in[25];
    const float* gg  = (const float*)d_in[26]; const float* gB  = (const float*)d_in[27];
    const float* gWz = (const float*)d_in[28]; const float* gbz = (const float*)d_in[29];
    const float* gWc = (const float*)d_in[30]; const float* gbc = (const float*)d_in[31];

    wm_kernel<<<NBLK, TPB>>>(tokens, actions, gpost, gprior,
                             pW1, pb1, pg1, pB1, pW2, pb2, pg2, pB2, pWo, pbo,
                             qW1, qb1, qg1, qB1, qW2, qb2, qg2, qB2, qWo, qbo,
                             gW, gb, gg, gB, gWz, gbz, gWc, gbc,
                             (float*)d_out);
}

// round 13
// speedup vs baseline: 2.0527x; 2.0527x over previous
#include <cuda_runtime.h>
#include <cstddef>

// ===========================================================================
// WorldModel RSSM persistent kernel. 512 threads/block (128-reg budget),
// R8C4 GEMM tiles with rotating 8-deep weight prefetch.
// S=32 C=32 D=4096 H=1024 A=6 B=16 T=64 TOK=4096, out feats [16,64,5120]
// ===========================================================================

#define NBLK 148
#define TPB  512
#define GPB  2                  // 256-thread groups per block
#define NG   (NBLK * GPB)       // 296 groups

#define CH_Q1 32                // prior layer1:  K=4096, Kc=128
#define CH_P1 64                // post  layer1:  K=8192, Kc=128
#define CH_L  16                // layers 2/3:    K=1024, Kc=64
#define CH_ZC 16                // z/cand:        K=5120, Kc=320

// ---------------------------------------------------------------------------
// Device scratch
// ---------------------------------------------------------------------------
__device__ float g_deter[16 * 4096];
__device__ float g_gx[16 * 1024];
__device__ float g_hqA[16 * 1024];
__device__ float g_hqB[16 * 1024];
__device__ float g_hpA[16 * 1024];
__device__ float g_hpB[16 * 1024];
__device__ float g_partQ[CH_Q1 * 16 * 1024];
__device__ float g_partP[CH_P1 * 16 * 1024];
__device__ float g_partZ[CH_ZC * 16 * 4096];
__device__ float g_partC[CH_ZC * 16 * 4096];
__device__ unsigned g_count;
__device__ unsigned g_gen;

// ---------------------------------------------------------------------------
__device__ __forceinline__ float2 ffma2(float2 a, float2 b, float2 c) {
    union U { float2 f; unsigned long long u; };
    U ua, ub, uc, ud;
    ua.f = a; ub.f = b; uc.f = c;
    asm("fma.rn.f32x2 %0, %1, %2, %3;"
        : "=l"(ud.u) : "l"(ua.u), "l"(ub.u), "l"(uc.u));
    return ud.f;
}

__device__ __forceinline__ void gbar() {
    __syncthreads();
    if (threadIdx.x == 0) {
        volatile unsigned* vg = &g_gen;
        unsigned gen = *vg;
        __threadfence();
        if (atomicAdd(&g_count, 1u) == NBLK - 1) {
            g_count = 0;
            __threadfence();
            *vg = gen + 1;
        } else {
            while (*vg == gen) { __nanosleep(32); }
        }
        __threadfence();
    }
    __syncthreads();
}

// block-wide sum over 512 threads
__device__ __forceinline__ float blockReduceSum(float v, float* sred) {
    int lane = threadIdx.x & 31, wid = threadIdx.x >> 5;
#pragma unroll
    for (int o = 16; o; o >>= 1) v += __shfl_xor_sync(0xffffffffu, v, o);
    __syncthreads();
    if (lane == 0) sred[wid] = v;
    __syncthreads();
    if (wid == 0) {
        float t = (lane < 16) ? sred[lane] : 0.f;
#pragma unroll
        for (int o = 8; o; o >>= 1) t += __shfl_xor_sync(0xffffffffu, t, o);
        if (lane == 0) sred[0] = t;
    }
    __syncthreads();
    return sred[0];
}

struct InDesc { const float* A; int strideA; int offA; int KA; const float* B; };

// R rows x 4 cols of FMA for one k slice (sAk = &sA[kk*R])
template <int R>
__device__ __forceinline__ void fmaR(const float* sAk, float4 w, float2* acc) {
    float2 wx = make_float2(w.x, w.x), wy = make_float2(w.y, w.y);
    float2 wz = make_float2(w.z, w.z), ww = make_float2(w.w, w.w);
    const float4* A4 = (const float4*)sAk;
    float4 a0 = A4[0];
    float2 p0 = make_float2(a0.x, a0.y), p1 = make_float2(a0.z, a0.w);
    acc[0] = ffma2(p0, wx, acc[0]); acc[1] = ffma2(p0, wy, acc[1]);
    acc[2] = ffma2(p0, wz, acc[2]); acc[3] = ffma2(p0, ww, acc[3]);
    acc[4] = ffma2(p1, wx, acc[4]); acc[5] = ffma2(p1, wy, acc[5]);
    acc[6] = ffma2(p1, wz, acc[6]); acc[7] = ffma2(p1, ww, acc[7]);
    if (R == 8) {
        float4 a1 = A4[1];
        float2 p2 = make_float2(a1.x, a1.y), p3 = make_float2(a1.z, a1.w);
        acc[8]  = ffma2(p2, wx, acc[8]);  acc[9]  = ffma2(p2, wy, acc[9]);
        acc[10] = ffma2(p2, wz, acc[10]); acc[11] = ffma2(p2, ww, acc[11]);
        acc[12] = ffma2(p3, wx, acc[12]); acc[13] = ffma2(p3, wy, acc[13]);
        acc[14] = ffma2(p3, wz, acc[14]); acc[15] = ffma2(p3, ww, acc[15]);
    }
}

// ---------------------------------------------------------------------------
// GEMM tile: R rows (8 or 4) x 1024 cols (256 threads x 4 cols, LDG.128),
// rotating 8-deep weight prefetch; A chunk staged to smem once.
// ---------------------------------------------------------------------------
template <int R>
__device__ __forceinline__ void gemm_g(
    InDesc in, const float4* __restrict__ W4, int N4,
    int c4base, int rowbase, int k0, int Kc,
    float4* __restrict__ part4, int chunkIdx,
    float* sA, int gtid, int barId)
{
    // stage A[rowbase..rowbase+R-1][k0..k0+Kc) -> sA[k*R + r]
    const int RM = R - 1, RS = (R == 8) ? 3 : 2;
    for (int idx = gtid; idx < R * Kc; idx += 256) {
        int k = idx >> RS, r = idx & RM;
        int row = rowbase + r, gk = k0 + k;
        float v = (gk < in.KA) ? in.A[(size_t)row * in.strideA + in.offA + gk]
                               : in.B[(size_t)row * 4096 + (gk - in.KA)];
        sA[idx] = v;
    }
    asm volatile("bar.sync %0, %1;" :: "r"(barId), "r"(256) : "memory");

    float2 acc[2 * R];
#pragma unroll
    for (int i = 0; i < 2 * R; i++) acc[i] = make_float2(0.f, 0.f);

    int col4 = c4base + gtid;
    const float4* Wp = W4 + (size_t)k0 * N4 + col4;
    const size_t step = N4;

    float4 w[8];
#pragma unroll
    for (int j = 0; j < 8; j++) { w[j] = __ldg(Wp); Wp += step; }

    for (int kb = 0; kb + 8 < Kc; kb += 8) {
#pragma unroll
        for (int j = 0; j < 8; j++) {
            fmaR<R>(sA + (kb + j) * R, w[j], acc);
            w[j] = __ldg(Wp); Wp += step;           // prefetch k = kb+8+j
        }
    }
#pragma unroll
    for (int j = 0; j < 8; j++) fmaR<R>(sA + (Kc - 8 + j) * R, w[j], acc);

    asm volatile("bar.sync %0, %1;" :: "r"(barId), "r"(256) : "memory");

#pragma unroll
    for (int r = 0; r < R; r++) {
        int rp = r >> 1;
        float4 o;
        if (r & 1) o = make_float4(acc[rp*4+0].y, acc[rp*4+1].y, acc[rp*4+2].y, acc[rp*4+3].y);
        else       o = make_float4(acc[rp*4+0].x, acc[rp*4+1].x, acc[rp*4+2].x, acc[rp*4+3].x);
        part4[(size_t)(chunkIdx * 16 + rowbase + r) * N4 + col4] = o;
    }
}

// ---------------------------------------------------------------------------
// Phase: fused layer-1 GEMMs. q: deter@qW1 (K=4096); p: [tok,deter]@pW1.
// 192 tiles.
// ---------------------------------------------------------------------------
__device__ void phase_g1(bool doq, bool dop, int tp, const float* tokens,
                         const float4* qW1, const float4* pW1,
                         float* sMy, int gtid, int gid2, int barId)
{
    int qT = doq ? (2 * CH_Q1) : 0;
    int total = qT + (dop ? (2 * CH_P1) : 0);
    for (int t = gid2; t < total; t += NG) {
        if (t < qT) {
            int ch = t >> 1, rh = t & 1;
            InDesc in = { g_deter, 4096, 0, 4096, g_deter };
            gemm_g<8>(in, qW1, 256, 0, rh * 8, ch * 128, 128,
                      (float4*)g_partQ, ch, sMy, gtid, barId);
        } else {
            int u = t - qT;
            int ch = u >> 1, rh = u & 1;
            InDesc in = { tokens, 64 * 4096, tp * 4096, 4096, g_deter };
            gemm_g<8>(in, pW1, 256, 0, rh * 8, ch * 128, 128,
                      (float4*)g_partP, ch, sMy, gtid, barId);
        }
    }
}

// ---------------------------------------------------------------------------
// Phase: fused layer-2/3 GEMMs (K=1024, Kc=64). 128 tiles.
// ---------------------------------------------------------------------------
__device__ void phase_g23(bool doq, bool dop,
                          const float4* Wq, const float4* Wp,
                          const float* inq, const float* inp,
                          float* sMy, int gtid, int gid2, int barId)
{
    int qT = doq ? (4 * CH_L) : 0;
    int total = qT + (dop ? (4 * CH_L) : 0);
    for (int t = gid2; t < total; t += NG) {
        bool isq = t < qT;
        int u = isq ? t : (t - qT);
        int ch = u >> 2, rq = u & 3;
        InDesc in = { isq ? inq : inp, 1024, 0, 1024, isq ? inq : inp };
        gemm_g<4>(in, isq ? Wq : Wp, 256, 0, rq * 4, ch * 64, 64,
                  (float4*)(isq ? g_partQ : g_partP), ch, sMy, gtid, barId);
    }
}

// ---------------------------------------------------------------------------
// Phase: z/cand GEMM. in=[gx,deter] K=5120, Kc=320, N=4096 each. 256 tiles.
// ---------------------------------------------------------------------------
__device__ void phase_zc(const float4* Wz, const float4* Wc,
                         float* sMy, int gtid, int gid2, int barId)
{
    const int total = 2 * 8 * CH_ZC;            // 256
    for (int t = gid2; t < total; t += NG) {
        bool isZ = t < 128;
        int u = t & 127;
        int ch = u >> 3, sub = u & 7;
        int ct = sub >> 1, rh = sub & 1;
        InDesc in = { g_gx, 1024, 0, 1024, g_deter };
        gemm_g<8>(in, isZ ? Wz : Wc, 1024, ct * 256, rh * 8, ch * 320, 320,
                  (float4*)(isZ ? g_partZ : g_partC), ch, sMy, gtid, barId);
    }
}

// ---------------------------------------------------------------------------
// Phase: reduce partials + bias + LN + SiLU. Blocks 0..15 q, 16..31 p.
// 512 threads: s = tid&255 (float4 col), qd = tid>>8 (2-way chunk split).
// ---------------------------------------------------------------------------
__device__ void phase_ln(bool doq, bool dop,
                         const float* qb, const float* qg, const float* qB,
                         const float* pb, const float* pg, const float* pB,
                         int chq, int chp, float* outq, float* outp,
                         float4* sLN, float* sred)
{
    int b = blockIdx.x;
    bool active = (b < 32);
    bool isq = b < 16;
    if (active && (isq ? !doq : !dop)) active = false;

    int s = threadIdx.x & 255, qd = threadIdx.x >> 8;
    float4 v = make_float4(0.f, 0.f, 0.f, 0.f);
    if (active) {
        int r = b & 15;
        const float4* part4 = (const float4*)(isq ? g_partQ : g_partP);
        int chunks = isq ? chq : chp;
        for (int ch = qd; ch < chunks; ch += 2) {
            float4 a = part4[(size_t)(ch * 16 + r) * 256 + s];
            v.x += a.x; v.y += a.y; v.z += a.z; v.w += a.w;
        }
    }
    sLN[qd * 256 + s] = v;
    __syncthreads();

    float4 tot = make_float4(0.f, 0.f, 0.f, 0.f);
    float partial = 0.f;
    if (active && qd == 0) {
        float4 a0 = sLN[s], a1 = sLN[256 + s];
        const float4* bias4 = (const float4*)(isq ? qb : pb);
        float4 bb = bias4[s];
        tot.x = a0.x + a1.x + bb.x;
        tot.y = a0.y + a1.y + bb.y;
        tot.z = a0.z + a1.z + bb.z;
        tot.w = a0.w + a1.w + bb.w;
        partial = tot.x + tot.y + tot.z + tot.w;
    }
    float mean = blockReduceSum(partial, sred) * (1.0f / 1024.0f);

    float4 d = make_float4(tot.x - mean, tot.y - mean, tot.z - mean, tot.w - mean);
    float sq = (active && qd == 0) ? (d.x*d.x + d.y*d.y + d.z*d.z + d.w*d.w) : 0.f;
    float var = blockReduceSum(sq, sred) * (1.0f / 1024.0f);

    if (active && qd == 0) {
        int r = b & 15;
        float rstd = rsqrtf(var + 1e-5f);
        const float4* g4 = (const float4*)(isq ? qg : pg);
        const float4* B4 = (const float4*)(isq ? qB : pB);
        float4 gg = g4[s], BB = B4[s], x;
        x.x = d.x * rstd * gg.x + BB.x;
        x.y = d.y * rstd * gg.y + BB.y;
        x.z = d.z * rstd * gg.z + BB.z;
        x.w = d.w * rstd * gg.w + BB.w;
        float4 o;
        o.x = x.x / (1.f + expf(-x.x));
        o.y = x.y / (1.f + expf(-x.y));
        o.z = x.z / (1.f + expf(-x.z));
        o.w = x.w / (1.f + expf(-x.w));
        ((float4*)(isq ? outq : outp))[r * 256 + s] = o;
    }
}

// ---------------------------------------------------------------------------
// Merged sample + GRU-input. 512 threads = 16 warps; each warp handles 2 s.
// Blocks 0..15: prior sample -> out. Blocks 16..31: posterior -> sIdx -> grux.
// ---------------------------------------------------------------------------
__device__ void phase_sample_grux(bool doq, bool dop, int t, int tp,
                                  const float* qbo, const float* pbo,
                                  const float* gprior, const float* gpost,
                                  const float* actions,
                                  const float* gW, const float* gb,
                                  const float* gg, const float* gB,
                                  int* sIdx, float* sAct, float* sred,
                                  float* out)
{
    int b = blockIdx.x;
    bool isq = b < 16;
    bool samp = (b < 32) && (isq ? doq : dop);
    bool grux = (b >= 16) && (b < 32) && dop;
    int r = b & 15;
    int wid = threadIdx.x >> 5, lane = threadIdx.x & 31;

    if (grux && threadIdx.x < 6)
        sAct[threadIdx.x] = actions[((size_t)r * 64 + tp) * 6 + threadIdx.x];

    if (samp) {
#pragma unroll
        for (int half = 0; half < 2; half++) {
            int s = wid + half * 16;
            int col = s * 32 + lane;
            const float* part = isq ? g_partQ : g_partP;
            float logit = (isq ? qbo : pbo)[col];
#pragma unroll
            for (int ch = 0; ch < CH_L; ch++)
                logit += part[(size_t)(ch * 16 + r) * 1024 + col];

            float mx = logit;
#pragma unroll
            for (int o = 16; o; o >>= 1) mx = fmaxf(mx, __shfl_xor_sync(0xffffffffu, mx, o));
            float e = expf(logit - mx);
            float se = e;
#pragma unroll
            for (int o = 16; o; o >>= 1) se += __shfl_xor_sync(0xffffffffu, se, o);
            float p = 0.99f * (e / se) + (0.01f / 32.0f);

            int tt = isq ? t : tp;
            const float* gum = isq ? gprior : gpost;
            float score = logf(p) + gum[(size_t)((tt * 16 + r) * 32 + s) * 32 + lane];

            float bs = score; int bi = lane;
#pragma unroll
            for (int o = 16; o; o >>= 1) {
                float os = __shfl_xor_sync(0xffffffffu, bs, o);
                int   oi = __shfl_xor_sync(0xffffffffu, bi, o);
                if (os > bs || (os == bs && oi < bi)) { bs = os; bi = oi; }
            }
            if (isq) {
                out[((size_t)r * 64 + t) * 5120 + 4096 + col] = (lane == bi) ? 1.0f : 0.0f;
            } else if (lane == bi) {
                sIdx[s] = bi;
            }
        }
    }
    __syncthreads();

    float v[2] = {0.f, 0.f};
    if (grux) {
#pragma unroll
        for (int ci = 0; ci < 2; ci++) {
            int col = threadIdx.x + ci * 512;
            float a = gb[col];
#pragma unroll
            for (int s2 = 0; s2 < 32; s2++)
                a += gW[(size_t)(s2 * 32 + sIdx[s2]) * 1024 + col];
#pragma unroll
            for (int j = 0; j < 6; j++)
                a += sAct[j] * gW[(size_t)(1024 + j) * 1024 + col];
            v[ci] = a;
        }
    }
    float mean = blockReduceSum(grux ? (v[0] + v[1]) : 0.f, sred) * (1.0f / 1024.0f);
    float d0 = v[0] - mean, d1 = v[1] - mean;
    float var = blockReduceSum(grux ? (d0 * d0 + d1 * d1) : 0.f, sred) * (1.0f / 1024.0f);
    if (grux) {
        float rstd = rsqrtf(var + 1e-5f);
#pragma unroll
        for (int ci = 0; ci < 2; ci++) {
            int col = threadIdx.x + ci * 512;
            float d = (ci ? d1 : d0);
            float x = d * rstd * gg[col] + gB[col];
            g_gx[r * 1024 + col] = x / (1.0f + expf(-x));
        }
    }
}

// ---------------------------------------------------------------------------
// Phase: gate — reduce z/cand partials (4-lane split), update deter, write out.
// ---------------------------------------------------------------------------
__device__ void phase_gate(int t, const float* gbz, const float* gbc,
                           float* out)
{
    int gt = blockIdx.x * TPB + threadIdx.x;    // 75776 threads
    int q4 = gt & 3, slot = gt >> 2;            // 16384 float4 slots
    if (slot >= 16384) return;
    int b = slot >> 10, c4 = slot & 1023;

    const float4* pz4 = (const float4*)g_partZ;
    const float4* pc4 = (const float4*)g_partC;
    float4 zp = make_float4(0.f, 0.f, 0.f, 0.f);
    float4 cp = make_float4(0.f, 0.f, 0.f, 0.f);
#pragma unroll
    for (int ch = q4; ch < CH_ZC; ch += 4) {
        float4 a = pz4[(size_t)(ch * 16 + b) * 1024 + c4];
        float4 c = pc4[(size_t)(ch * 16 + b) * 1024 + c4];
        zp.x += a.x; zp.y += a.y; zp.z += a.z; zp.w += a.w;
        cp.x += c.x; cp.y += c.y; cp.z += c.z; cp.w += c.w;
    }
#pragma unroll
    for (int off = 2; off; off >>= 1) {
        zp.x += __shfl_down_sync(0xffffffffu, zp.x, off);
        zp.y += __shfl_down_sync(0xffffffffu, zp.y, off);
        zp.z += __shfl_down_sync(0xffffffffu, zp.z, off);
        zp.w += __shfl_down_sync(0xffffffffu, zp.w, off);
        cp.x += __shfl_down_sync(0xffffffffu, cp.x, off);
        cp.y += __shfl_down_sync(0xffffffffu, cp.y, off);
        cp.z += __shfl_down_sync(0xffffffffu, cp.z, off);
        cp.w += __shfl_down_sync(0xffffffffu, cp.w, off);
    }
    if (q4 == 0) {
        float4 bz = ((const float4*)gbz)[c4], bc = ((const float4*)gbc)[c4];
        zp.x += bz.x; zp.y += bz.y; zp.z += bz.z; zp.w += bz.w;
        cp.x += bc.x; cp.y += bc.y; cp.z += bc.z; cp.w += bc.w;
        float4* dt4 = (float4*)g_deter;
        float4 dv = dt4[b * 1024 + c4], dn;
        float z, cd;
        z = 1.f / (1.f + expf(-zp.x)); cd = tanhf(cp.x); dn.x = (1.f - z) * dv.x + z * cd;
        z = 1.f / (1.f + expf(-zp.y)); cd = tanhf(cp.y); dn.y = (1.f - z) * dv.y + z * cd;
        z = 1.f / (1.f + expf(-zp.z)); cd = tanhf(cp.z); dn.z = (1.f - z) * dv.z + z * cd;
        z = 1.f / (1.f + expf(-zp.w)); cd = tanhf(cp.w); dn.w = (1.f - z) * dv.w + z * cd;
        dt4[b * 1024 + c4] = dn;
        ((float4*)(out + ((size_t)b * 64 + t) * 5120))[c4] = dn;
    }
}

// ---------------------------------------------------------------------------
__global__ void __launch_bounds__(TPB, 1)
wm_kernel(const float* tokens, const float* actions,
          const float* gpost, const float* gprior,
          const float* pW1, const float* pb1, const float* pg1, const float* pB1,
          const float* pW2, const float* pb2, const float* pg2, const float* pB2,
          const float* pWo, const float* pbo,
          const float* qW1, const float* qb1, const float* qg1, const float* qB1,
          const float* qW2, const float* qb2, const float* qg2, const float* qB2,
          const float* qWo, const float* qbo,
          const float* gW, const float* gb, const float* gg, const float* gB,
          const float* gWz, const float* gbz, const float* gWc, const float* gbc,
          float* out)
{
    __shared__ float  sStage[GPB * 2560];      // 2 groups x 10 KB (8 x 320)
    __shared__ float4 sLN[512];
    __shared__ float  sRed[16];
    __shared__ int    sIdx[32];
    __shared__ float  sAct[6];

    int tid = threadIdx.x;
    int g = tid >> 8, gtid = tid & 255;
    int gid2 = g * NBLK + blockIdx.x;
    float* sMy = sStage + g * 2560;
    int barId = g + 1;

    const float4* pW1v = (const float4*)pW1; const float4* pW2v = (const float4*)pW2;
    const float4* pWov = (const float4*)pWo;
    const float4* qW1v = (const float4*)qW1; const float4* qW2v = (const float4*)qW2;
    const float4* qWov = (const float4*)qWo;
    const float4* gWzv = (const float4*)gWz; const float4* gWcv = (const float4*)gWc;

    for (int i = blockIdx.x * TPB + tid; i < 16 * 4096; i += NBLK * TPB)
        g_deter[i] = 0.0f;
    gbar();

    // prologue: posterior(0) + grux(0)
    phase_g1(false, true, 0, tokens, qW1v, pW1v, sMy, gtid, gid2, barId);      gbar();
    phase_ln(false, true, qb1, qg1, qB1, pb1, pg1, pB1, CH_Q1, CH_P1,
             g_hqA, g_hpA, sLN, sRed);                                         gbar();
    phase_g23(false, true, qW2v, pW2v, g_hqA, g_hpA, sMy, gtid, gid2, barId);  gbar();
    phase_ln(false, true, qb2, qg2, qB2, pb2, pg2, pB2, CH_L, CH_L,
             g_hqB, g_hpB, sLN, sRed);                                         gbar();
    phase_g23(false, true, qWov, pWov, g_hqB, g_hpB, sMy, gtid, gid2, barId);  gbar();
    phase_sample_grux(false, true, 0, 0, qbo, pbo, gprior, gpost,
                      actions, gW, gb, gg, gB, sIdx, sAct, sRed, out);         gbar();

    for (int t = 0; t < 64; t++) {
        phase_zc(gWzv, gWcv, sMy, gtid, gid2, barId);                          gbar();
        phase_gate(t, gbz, gbc, out);                                          gbar();

        bool dop = (t < 63);
        phase_g1(true, dop, t + 1, tokens, qW1v, pW1v, sMy, gtid, gid2, barId); gbar();
        phase_ln(true, dop, qb1, qg1, qB1, pb1, pg1, pB1, CH_Q1, CH_P1,
                 g_hqA, g_hpA, sLN, sRed);                                      gbar();
        phase_g23(true, dop, qW2v, pW2v, g_hqA, g_hpA, sMy, gtid, gid2, barId); gbar();
        phase_ln(true, dop, qb2, qg2, qB2, pb2, pg2, pB2, CH_L, CH_L,
                 g_hqB, g_hpB, sLN, sRed);                                      gbar();
        phase_g23(true, dop, qWov, pWov, g_hqB, g_hpB, sMy, gtid, gid2, barId); gbar();
        phase_sample_grux(true, dop, t, t + 1, qbo, pbo, gprior, gpost,
                          actions, gW, gb, gg, gB, sIdx, sAct, sRed, out);      gbar();
    }
}

// ---------------------------------------------------------------------------
extern "C" void kernel_launch(void* const* d_in, const int* in_sizes, int n_in,
                              void* d_out, int out_size) {
    const float* tokens  = (const float*)d_in[0];
    const float* actions = (const float*)d_in[1];
    const float* gpost   = (const float*)d_in[2];
    const float* gprior  = (const float*)d_in[3];
    const float* pW1 = (const float*)d_in[4];  const float* pb1 = (const float*)d_in[5];
    const float* pg1 = (const float*)d_in[6];  const float* pB1 = (const float*)d_in[7];
    const float* pW2 = (const float*)d_in[8];  const float* pb2 = (const float*)d_in[9];
    const float* pg2 = (const float*)d_in[10]; const float* pB2 = (const float*)d_in[11];
    const float* pWo = (const float*)d_in[12]; const float* pbo = (const float*)d_in[13];
    const float* qW1 = (const float*)d_in[14]; const float* qb1 = (const float*)d_in[15];
    const float* qg1 = (const float*)d_in[16]; const float* qB1 = (const float*)d_in[17];
    const float* qW2 = (const float*)d_in[18]; const float* qb2 = (const float*)d_in[19];
    const float* qg2 = (const float*)d_in[20]; const float* qB2 = (const float*)d_in[21];
    const float* qWo = (const float*)d_in[22]; const float* qbo = (const float*)d_in[23];
    const float* gW  = (const float*)d_in[24]; const float* gb  = (const float*)d_in[25];
    const float* gg  = (const float*)d_in[26]; const float* gB  = (const float*)d_in[27];
    const float* gWz = (const float*)d_in[28]; const float* gbz = (const float*)d_in[29];
    const float* gWc = (const float*)d_in[30]; const float* gbc = (const float*)d_in[31];

    wm_kernel<<<NBLK, TPB>>>(tokens, actions, gpost, gprior,
                             pW1, pb1, pg1, pB1, pW2, pb2, pg2, pB2, pWo, pbo,
                             qW1, qb1, qg1, qB1, qW2, qb2, qg2, qB2, qWo, qbo,
                             gW, gb, gg, gB, gWz, gbz, gWc, gbc,
                             (float*)d_out);
}

// round 14
// speedup vs baseline: 2.1431x; 1.0440x over previous
#include <cuda_runtime.h>
#include <cstddef>

// ===========================================================================
// WorldModel RSSM persistent kernel. cp.async smem-ring weight pipeline
// (8-deep, barrier-free: each thread consumes its own 16B stage slot).
// S=32 C=32 D=4096 H=1024 A=6 B=16 T=64 TOK=4096, out feats [16,64,5120]
// ===========================================================================

#define NBLK 148
#define TPB  512
#define GPB  2                  // 256-thread groups per block
#define NG   (NBLK * GPB)       // 296 groups

#define CH_Q1 32                // prior layer1:  K=4096, Kc=128
#define CH_P1 64                // post  layer1:  K=8192, Kc=128
#define CH_L  16                // layers 2/3:    K=1024, Kc=64
#define CH_ZC 16                // z/cand:        K=5120, Kc=320

// Dynamic smem layout (bytes):
//   [0, 20480)       sA: 2 groups x 2560 floats (A staging; sLN overlays grp0)
//   [20480, 86016)   sW: 2 groups x 8 stages x 256 float4 (weight ring)
#define SMEM_BYTES 86016

// ---------------------------------------------------------------------------
// Device scratch
// ---------------------------------------------------------------------------
__device__ float g_deter[16 * 4096];
__device__ float g_gx[16 * 1024];
__device__ float g_hqA[16 * 1024];
__device__ float g_hqB[16 * 1024];
__device__ float g_hpA[16 * 1024];
__device__ float g_hpB[16 * 1024];
__device__ float g_partQ[CH_Q1 * 16 * 1024];
__device__ float g_partP[CH_P1 * 16 * 1024];
__device__ float g_partZ[CH_ZC * 16 * 4096];
__device__ float g_partC[CH_ZC * 16 * 4096];
__device__ unsigned g_count;
__device__ unsigned g_gen;

// ---------------------------------------------------------------------------
__device__ __forceinline__ float2 ffma2(float2 a, float2 b, float2 c) {
    union U { float2 f; unsigned long long u; };
    U ua, ub, uc, ud;
    ua.f = a; ub.f = b; uc.f = c;
    asm("fma.rn.f32x2 %0, %1, %2, %3;"
        : "=l"(ud.u) : "l"(ua.u), "l"(ub.u), "l"(uc.u));
    return ud.f;
}

__device__ __forceinline__ void cpa16(unsigned saddr, const void* gptr) {
    asm volatile("cp.async.cg.shared.global [%0], [%1], 16;"
                 :: "r"(saddr), "l"(gptr));
}
#define CPA_COMMIT() asm volatile("cp.async.commit_group;" ::: "memory")
#define CPA_WAIT7()  asm volatile("cp.async.wait_group 7;" ::: "memory")

__device__ __forceinline__ void gbar() {
    __syncthreads();
    if (threadIdx.x == 0) {
        volatile unsigned* vg = &g_gen;
        unsigned gen = *vg;
        __threadfence();
        if (atomicAdd(&g_count, 1u) == NBLK - 1) {
            g_count = 0;
            __threadfence();
            *vg = gen + 1;
        } else {
            while (*vg == gen) { __nanosleep(32); }
        }
        __threadfence();
    }
    __syncthreads();
}

// block-wide sum over 512 threads
__device__ __forceinline__ float blockReduceSum(float v, float* sred) {
    int lane = threadIdx.x & 31, wid = threadIdx.x >> 5;
#pragma unroll
    for (int o = 16; o; o >>= 1) v += __shfl_xor_sync(0xffffffffu, v, o);
    __syncthreads();
    if (lane == 0) sred[wid] = v;
    __syncthreads();
    if (wid == 0) {
        float t = (lane < 16) ? sred[lane] : 0.f;
#pragma unroll
        for (int o = 8; o; o >>= 1) t += __shfl_xor_sync(0xffffffffu, t, o);
        if (lane == 0) sred[0] = t;
    }
    __syncthreads();
    return sred[0];
}

struct InDesc { const float* A; int strideA; int offA; int KA; const float* B; };

// R rows x 4 cols of FMA for one k slice (sAk = &sA[kk*R])
template <int R>
__device__ __forceinline__ void fmaR(const float* sAk, float4 w, float2* acc) {
    float2 wx = make_float2(w.x, w.x), wy = make_float2(w.y, w.y);
    float2 wz = make_float2(w.z, w.z), ww = make_float2(w.w, w.w);
    const float4* A4 = (const float4*)sAk;
    float4 a0 = A4[0];
    float2 p0 = make_float2(a0.x, a0.y), p1 = make_float2(a0.z, a0.w);
    acc[0] = ffma2(p0, wx, acc[0]); acc[1] = ffma2(p0, wy, acc[1]);
    acc[2] = ffma2(p0, wz, acc[2]); acc[3] = ffma2(p0, ww, acc[3]);
    acc[4] = ffma2(p1, wx, acc[4]); acc[5] = ffma2(p1, wy, acc[5]);
    acc[6] = ffma2(p1, wz, acc[6]); acc[7] = ffma2(p1, ww, acc[7]);
    if (R == 8) {
        float4 a1 = A4[1];
        float2 p2 = make_float2(a1.x, a1.y), p3 = make_float2(a1.z, a1.w);
        acc[8]  = ffma2(p2, wx, acc[8]);  acc[9]  = ffma2(p2, wy, acc[9]);
        acc[10] = ffma2(p2, wz, acc[10]); acc[11] = ffma2(p2, ww, acc[11]);
        acc[12] = ffma2(p3, wx, acc[12]); acc[13] = ffma2(p3, wy, acc[13]);
        acc[14] = ffma2(p3, wz, acc[14]); acc[15] = ffma2(p3, ww, acc[15]);
    }
}

// ---------------------------------------------------------------------------
// GEMM tile: R rows (8 or 4) x 1024 cols (256 threads x 4 cols). Weights
// streamed through an 8-stage per-thread smem ring via cp.async.cg; the
// inner loop has NO barriers (each thread reads only its own slot).
// ---------------------------------------------------------------------------
template <int R>
__device__ __forceinline__ void gemm_g(
    InDesc in, const float4* __restrict__ W4, int N4,
    int c4base, int rowbase, int k0, int Kc,
    float4* __restrict__ part4, int chunkIdx,
    float* sA, float4* sW, int gtid, int barId)
{
    // stage A[rowbase..rowbase+R-1][k0..k0+Kc) -> sA[k*R + r]
    const int RM = R - 1, RS = (R == 8) ? 3 : 2;
    for (int idx = gtid; idx < R * Kc; idx += 256) {
        int k = idx >> RS, r = idx & RM;
        int row = rowbase + r, gk = k0 + k;
        float v = (gk < in.KA) ? in.A[(size_t)row * in.strideA + in.offA + gk]
                               : in.B[(size_t)row * 4096 + (gk - in.KA)];
        sA[idx] = v;
    }
    asm volatile("bar.sync %0, %1;" :: "r"(barId), "r"(256) : "memory");

    float2 acc[2 * R];
#pragma unroll
    for (int i = 0; i < 2 * R; i++) acc[i] = make_float2(0.f, 0.f);

    int col4 = c4base + gtid;
    const float4* Wp = W4 + (size_t)k0 * N4 + col4;
    const size_t step = N4;

    // my slot in each ring stage
    unsigned swaddr = (unsigned)__cvta_generic_to_shared(sW + gtid);

    // prologue: fill 8 stages
#pragma unroll
    for (int j = 0; j < 8; j++) {
        cpa16(swaddr + (unsigned)j * 4096u, Wp); Wp += step;
        CPA_COMMIT();
    }

    for (int kk = 0; kk < Kc; kk++) {
        CPA_WAIT7();                                    // stage kk landed
        float4 w = sW[(kk & 7) * 256 + gtid];
        fmaR<R>(sA + kk * R, w, acc);
        if (kk + 8 < Kc) { cpa16(swaddr + (unsigned)(kk & 7) * 4096u, Wp); Wp += step; }
        CPA_COMMIT();                                   // keep group count exact
    }

    asm volatile("bar.sync %0, %1;" :: "r"(barId), "r"(256) : "memory");

#pragma unroll
    for (int r = 0; r < R; r++) {
        int rp = r >> 1;
        float4 o;
        if (r & 1) o = make_float4(acc[rp*4+0].y, acc[rp*4+1].y, acc[rp*4+2].y, acc[rp*4+3].y);
        else       o = make_float4(acc[rp*4+0].x, acc[rp*4+1].x, acc[rp*4+2].x, acc[rp*4+3].x);
        part4[(size_t)(chunkIdx * 16 + rowbase + r) * N4 + col4] = o;
    }
}

// ---------------------------------------------------------------------------
// Phase: fused layer-1 GEMMs. q: deter@qW1 (K=4096); p: [tok,deter]@pW1.
// ---------------------------------------------------------------------------
__device__ void phase_g1(bool doq, bool dop, int tp, const float* tokens,
                         const float4* qW1, const float4* pW1,
                         float* sMy, float4* sWMy, int gtid, int gid2, int barId)
{
    int qT = doq ? (2 * CH_Q1) : 0;
    int total = qT + (dop ? (2 * CH_P1) : 0);
    for (int t = gid2; t < total; t += NG) {
        if (t < qT) {
            int ch = t >> 1, rh = t & 1;
            InDesc in = { g_deter, 4096, 0, 4096, g_deter };
            gemm_g<8>(in, qW1, 256, 0, rh * 8, ch * 128, 128,
                      (float4*)g_partQ, ch, sMy, sWMy, gtid, barId);
        } else {
            int u = t - qT;
            int ch = u >> 1, rh = u & 1;
            InDesc in = { tokens, 64 * 4096, tp * 4096, 4096, g_deter };
            gemm_g<8>(in, pW1, 256, 0, rh * 8, ch * 128, 128,
                      (float4*)g_partP, ch, sMy, sWMy, gtid, barId);
        }
    }
}

// ---------------------------------------------------------------------------
// Phase: fused layer-2/3 GEMMs (K=1024, Kc=64).
// ---------------------------------------------------------------------------
__device__ void phase_g23(bool doq, bool dop,
                          const float4* Wq, const float4* Wp,
                          const float* inq, const float* inp,
                          float* sMy, float4* sWMy, int gtid, int gid2, int barId)
{
    int qT = doq ? (4 * CH_L) : 0;
    int total = qT + (dop ? (4 * CH_L) : 0);
    for (int t = gid2; t < total; t += NG) {
        bool isq = t < qT;
        int u = isq ? t : (t - qT);
        int ch = u >> 2, rq = u & 3;
        InDesc in = { isq ? inq : inp, 1024, 0, 1024, isq ? inq : inp };
        gemm_g<4>(in, isq ? Wq : Wp, 256, 0, rq * 4, ch * 64, 64,
                  (float4*)(isq ? g_partQ : g_partP), ch, sMy, sWMy, gtid, barId);
    }
}

// ---------------------------------------------------------------------------
// Phase: z/cand GEMM. in=[gx,deter] K=5120, Kc=320, N=4096 each. 256 tiles.
// ---------------------------------------------------------------------------
__device__ void phase_zc(const float4* Wz, const float4* Wc,
                         float* sMy, float4* sWMy, int gtid, int gid2, int barId)
{
    const int total = 2 * 8 * CH_ZC;            // 256
    for (int t = gid2; t < total; t += NG) {
        bool isZ = t < 128;
        int u = t & 127;
        int ch = u >> 3, sub = u & 7;
        int ct = sub >> 1, rh = sub & 1;
        InDesc in = { g_gx, 1024, 0, 1024, g_deter };
        gemm_g<8>(in, isZ ? Wz : Wc, 1024, ct * 256, rh * 8, ch * 320, 320,
                  (float4*)(isZ ? g_partZ : g_partC), ch, sMy, sWMy, gtid, barId);
    }
}

// ---------------------------------------------------------------------------
// Phase: reduce partials + bias + LN + SiLU. Blocks 0..15 q, 16..31 p.
// ---------------------------------------------------------------------------
__device__ void phase_ln(bool doq, bool dop,
                         const float* qb, const float* qg, const float* qB,
                         const float* pb, const float* pg, const float* pB,
                         int chq, int chp, float* outq, float* outp,
                         float4* sLN, float* sred)
{
    int b = blockIdx.x;
    bool active = (b < 32);
    bool isq = b < 16;
    if (active && (isq ? !doq : !dop)) active = false;

    int s = threadIdx.x & 255, qd = threadIdx.x >> 8;
    float4 v = make_float4(0.f, 0.f, 0.f, 0.f);
    if (active) {
        int r = b & 15;
        const float4* part4 = (const float4*)(isq ? g_partQ : g_partP);
        int chunks = isq ? chq : chp;
        for (int ch = qd; ch < chunks; ch += 2) {
            float4 a = part4[(size_t)(ch * 16 + r) * 256 + s];
            v.x += a.x; v.y += a.y; v.z += a.z; v.w += a.w;
        }
    }
    sLN[qd * 256 + s] = v;
    __syncthreads();

    float4 tot = make_float4(0.f, 0.f, 0.f, 0.f);
    float partial = 0.f;
    if (active && qd == 0) {
        float4 a0 = sLN[s], a1 = sLN[256 + s];
        const float4* bias4 = (const float4*)(isq ? qb : pb);
        float4 bb = bias4[s];
        tot.x = a0.x + a1.x + bb.x;
        tot.y = a0.y + a1.y + bb.y;
        tot.z = a0.z + a1.z + bb.z;
        tot.w = a0.w + a1.w + bb.w;
        partial = tot.x + tot.y + tot.z + tot.w;
    }
    float mean = blockReduceSum(partial, sred) * (1.0f / 1024.0f);

    float4 d = make_float4(tot.x - mean, tot.y - mean, tot.z - mean, tot.w - mean);
    float sq = (active && qd == 0) ? (d.x*d.x + d.y*d.y + d.z*d.z + d.w*d.w) : 0.f;
    float var = blockReduceSum(sq, sred) * (1.0f / 1024.0f);

    if (active && qd == 0) {
        int r = b & 15;
        float rstd = rsqrtf(var + 1e-5f);
        const float4* g4 = (const float4*)(isq ? qg : pg);
        const float4* B4 = (const float4*)(isq ? qB : pB);
        float4 gg = g4[s], BB = B4[s], x;
        x.x = d.x * rstd * gg.x + BB.x;
        x.y = d.y * rstd * gg.y + BB.y;
        x.z = d.z * rstd * gg.z + BB.z;
        x.w = d.w * rstd * gg.w + BB.w;
        float4 o;
        o.x = x.x / (1.f + expf(-x.x));
        o.y = x.y / (1.f + expf(-x.y));
        o.z = x.z / (1.f + expf(-x.z));
        o.w = x.w / (1.f + expf(-x.w));
        ((float4*)(isq ? outq : outp))[r * 256 + s] = o;
    }
}

// ---------------------------------------------------------------------------
// Merged sample + GRU-input. 512 threads = 16 warps; each warp handles 2 s.
// Blocks 0..15: prior sample -> out. Blocks 16..31: posterior -> sIdx -> grux.
// ---------------------------------------------------------------------------
__device__ void phase_sample_grux(bool doq, bool dop, int t, int tp,
                                  const float* qbo, const float* pbo,
                                  const float* gprior, const float* gpost,
                                  const float* actions,
                                  const float* gW, const float* gb,
                                  const float* gg, const float* gB,
                                  int* sIdx, float* sAct, float* sred,
                                  float* out)
{
    int b = blockIdx.x;
    bool isq = b < 16;
    bool samp = (b < 32) && (isq ? doq : dop);
    bool grux = (b >= 16) && (b < 32) && dop;
    int r = b & 15;
    int wid = threadIdx.x >> 5, lane = threadIdx.x & 31;

    if (grux && threadIdx.x < 6)
        sAct[threadIdx.x] = actions[((size_t)r * 64 + tp) * 6 + threadIdx.x];

    if (samp) {
#pragma unroll
        for (int half = 0; half < 2; half++) {
            int s = wid + half * 16;
            int col = s * 32 + lane;
            const float* part = isq ? g_partQ : g_partP;
            float logit = (isq ? qbo : pbo)[col];
#pragma unroll
            for (int ch = 0; ch < CH_L; ch++)
                logit += part[(size_t)(ch * 16 + r) * 1024 + col];

            float mx = logit;
#pragma unroll
            for (int o = 16; o; o >>= 1) mx = fmaxf(mx, __shfl_xor_sync(0xffffffffu, mx, o));
            float e = expf(logit - mx);
            float se = e;
#pragma unroll
            for (int o = 16; o; o >>= 1) se += __shfl_xor_sync(0xffffffffu, se, o);
            float p = 0.99f * (e / se) + (0.01f / 32.0f);

            int tt = isq ? t : tp;
            const float* gum = isq ? gprior : gpost;
            float score = logf(p) + gum[(size_t)((tt * 16 + r) * 32 + s) * 32 + lane];

            float bs = score; int bi = lane;
#pragma unroll
            for (int o = 16; o; o >>= 1) {
                float os = __shfl_xor_sync(0xffffffffu, bs, o);
                int   oi = __shfl_xor_sync(0xffffffffu, bi, o);
                if (os > bs || (os == bs && oi < bi)) { bs = os; bi = oi; }
            }
            if (isq) {
                out[((size_t)r * 64 + t) * 5120 + 4096 + col] = (lane == bi) ? 1.0f : 0.0f;
            } else if (lane == bi) {
                sIdx[s] = bi;
            }
        }
    }
    __syncthreads();

    float v[2] = {0.f, 0.f};
    if (grux) {
#pragma unroll
        for (int ci = 0; ci < 2; ci++) {
            int col = threadIdx.x + ci * 512;
            float a = gb[col];
#pragma unroll
            for (int s2 = 0; s2 < 32; s2++)
                a += gW[(size_t)(s2 * 32 + sIdx[s2]) * 1024 + col];
#pragma unroll
            for (int j = 0; j < 6; j++)
                a += sAct[j] * gW[(size_t)(1024 + j) * 1024 + col];
            v[ci] = a;
        }
    }
    float mean = blockReduceSum(grux ? (v[0] + v[1]) : 0.f, sred) * (1.0f / 1024.0f);
    float d0 = v[0] - mean, d1 = v[1] - mean;
    float var = blockReduceSum(grux ? (d0 * d0 + d1 * d1) : 0.f, sred) * (1.0f / 1024.0f);
    if (grux) {
        float rstd = rsqrtf(var + 1e-5f);
#pragma unroll
        for (int ci = 0; ci < 2; ci++) {
            int col = threadIdx.x + ci * 512;
            float d = (ci ? d1 : d0);
            float x = d * rstd * gg[col] + gB[col];
            g_gx[r * 1024 + col] = x / (1.0f + expf(-x));
        }
    }
}

// ---------------------------------------------------------------------------
// Phase: gate — reduce z/cand partials (4-lane split), update deter, write out.
// ---------------------------------------------------------------------------
__device__ void phase_gate(int t, const float* gbz, const float* gbc,
                           float* out)
{
    int gt = blockIdx.x * TPB + threadIdx.x;    // 75776 threads
    int q4 = gt & 3, slot = gt >> 2;            // 16384 float4 slots
    if (slot >= 16384) return;
    int b = slot >> 10, c4 = slot & 1023;

    const float4* pz4 = (const float4*)g_partZ;
    const float4* pc4 = (const float4*)g_partC;
    float4 zp = make_float4(0.f, 0.f, 0.f, 0.f);
    float4 cp = make_float4(0.f, 0.f, 0.f, 0.f);
#pragma unroll
    for (int ch = q4; ch < CH_ZC; ch += 4) {
        float4 a = pz4[(size_t)(ch * 16 + b) * 1024 + c4];
        float4 c = pc4[(size_t)(ch * 16 + b) * 1024 + c4];
        zp.x += a.x; zp.y += a.y; zp.z += a.z; zp.w += a.w;
        cp.x += c.x; cp.y += c.y; cp.z += c.z; cp.w += c.w;
    }
#pragma unroll
    for (int off = 2; off; off >>= 1) {
        zp.x += __shfl_down_sync(0xffffffffu, zp.x, off);
        zp.y += __shfl_down_sync(0xffffffffu, zp.y, off);
        zp.z += __shfl_down_sync(0xffffffffu, zp.z, off);
        zp.w += __shfl_down_sync(0xffffffffu, zp.w, off);
        cp.x += __shfl_down_sync(0xffffffffu, cp.x, off);
        cp.y += __shfl_down_sync(0xffffffffu, cp.y, off);
        cp.z += __shfl_down_sync(0xffffffffu, cp.z, off);
        cp.w += __shfl_down_sync(0xffffffffu, cp.w, off);
    }
    if (q4 == 0) {
        float4 bz = ((const float4*)gbz)[c4], bc = ((const float4*)gbc)[c4];
        zp.x += bz.x; zp.y += bz.y; zp.z += bz.z; zp.w += bz.w;
        cp.x += bc.x; cp.y += bc.y; cp.z += bc.z; cp.w += bc.w;
        float4* dt4 = (float4*)g_deter;
        float4 dv = dt4[b * 1024 + c4], dn;
        float z, cd;
        z = 1.f / (1.f + expf(-zp.x)); cd = tanhf(cp.x); dn.x = (1.f - z) * dv.x + z * cd;
        z = 1.f / (1.f + expf(-zp.y)); cd = tanhf(cp.y); dn.y = (1.f - z) * dv.y + z * cd;
        z = 1.f / (1.f + expf(-zp.z)); cd = tanhf(cp.z); dn.z = (1.f - z) * dv.z + z * cd;
        z = 1.f / (1.f + expf(-zp.w)); cd = tanhf(cp.w); dn.w = (1.f - z) * dv.w + z * cd;
        dt4[b * 1024 + c4] = dn;
        ((float4*)(out + ((size_t)b * 64 + t) * 5120))[c4] = dn;
    }
}

// ---------------------------------------------------------------------------
__global__ void __launch_bounds__(TPB, 1)
wm_kernel(const float* tokens, const float* actions,
          const float* gpost, const float* gprior,
          const float* pW1, const float* pb1, const float* pg1, const float* pB1,
          const float* pW2, const float* pb2, const float* pg2, const float* pB2,
          const float* pWo, const float* pbo,
          const float* qW1, const float* qb1, const float* qg1, const float* qB1,
          const float* qW2, const float* qb2, const float* qg2, const float* qB2,
          const float* qWo, const float* qbo,
          const float* gW, const float* gb, const float* gg, const float* gB,
          const float* gWz, const float* gbz, const float* gWc, const float* gbc,
          float* out)
{
    extern __shared__ char dynsmem[];
    float*  sA_all = (float*)dynsmem;                       // 2 x 2560 floats
    float4* sW_all = (float4*)(dynsmem + 20480);            // 2 x 2048 float4
    float4* sLN    = (float4*)dynsmem;                      // overlay (LN only)
    __shared__ float sRed[16];
    __shared__ int   sIdx[32];
    __shared__ float sAct[6];

    int tid = threadIdx.x;
    int g = tid >> 8, gtid = tid & 255;
    int gid2 = g * NBLK + blockIdx.x;
    float*  sMy  = sA_all + g * 2560;
    float4* sWMy = sW_all + g * 2048;
    int barId = g + 1;

    const float4* pW1v = (const float4*)pW1; const float4* pW2v = (const float4*)pW2;
    const float4* pWov = (const float4*)pWo;
    const float4* qW1v = (const float4*)qW1; const float4* qW2v = (const float4*)qW2;
    const float4* qWov = (const float4*)qWo;
    const float4* gWzv = (const float4*)gWz; const float4* gWcv = (const float4*)gWc;

    for (int i = blockIdx.x * TPB + tid; i < 16 * 4096; i += NBLK * TPB)
        g_deter[i] = 0.0f;
    gbar();

    // prologue: posterior(0) + grux(0)
    phase_g1(false, true, 0, tokens, qW1v, pW1v, sMy, sWMy, gtid, gid2, barId);   gbar();
    phase_ln(false, true, qb1, qg1, qB1, pb1, pg1, pB1, CH_Q1, CH_P1,
             g_hqA, g_hpA, sLN, sRed);                                            gbar();
    phase_g23(false, true, qW2v, pW2v, g_hqA, g_hpA, sMy, sWMy, gtid, gid2, barId); gbar();
    phase_ln(false, true, qb2, qg2, qB2, pb2, pg2, pB2, CH_L, CH_L,
             g_hqB, g_hpB, sLN, sRed);                                            gbar();
    phase_g23(false, true, qWov, pWov, g_hqB, g_hpB, sMy, sWMy, gtid, gid2, barId); gbar();
    phase_sample_grux(false, true, 0, 0, qbo, pbo, gprior, gpost,
                      actions, gW, gb, gg, gB, sIdx, sAct, sRed, out);            gbar();

    for (int t = 0; t < 64; t++) {
        phase_zc(gWzv, gWcv, sMy, sWMy, gtid, gid2, barId);                       gbar();
        phase_gate(t, gbz, gbc, out);                                             gbar();

        bool dop = (t < 63);
        phase_g1(true, dop, t + 1, tokens, qW1v, pW1v, sMy, sWMy, gtid, gid2, barId); gbar();
        phase_ln(true, dop, qb1, qg1, qB1, pb1, pg1, pB1, CH_Q1, CH_P1,
                 g_hqA, g_hpA, sLN, sRed);                                            gbar();
        phase_g23(true, dop, qW2v, pW2v, g_hqA, g_hpA, sMy, sWMy, gtid, gid2, barId); gbar();
        phase_ln(true, dop, qb2, qg2, qB2, pb2, pg2, pB2, CH_L, CH_L,
                 g_hqB, g_hpB, sLN, sRed);                                            gbar();
        phase_g23(true, dop, qWov, pWov, g_hqB, g_hpB, sMy, sWMy, gtid, gid2, barId); gbar();
        phase_sample_grux(true, dop, t, t + 1, qbo, pbo, gprior, gpost,
                          actions, gW, gb, gg, gB, sIdx, sAct, sRed, out);            gbar();
    }
}

// ---------------------------------------------------------------------------
extern "C" void kernel_launch(void* const* d_in, const int* in_sizes, int n_in,
                              void* d_out, int out_size) {
    const float* tokens  = (const float*)d_in[0];
    const float* actions = (const float*)d_in[1];
    const float* gpost   = (const float*)d_in[2];
    const float* gprior  = (const float*)d_in[3];
    const float* pW1 = (const float*)d_in[4];  const float* pb1 = (const float*)d_in[5];
    const float* pg1 = (const float*)d_in[6];  const float* pB1 = (const float*)d_in[7];
    const float* pW2 = (const float*)d_in[8];  const float* pb2 = (const float*)d_in[9];
    const float* pg2 = (const float*)d_in[10]; const float* pB2 = (const float*)d_in[11];
    const float* pWo = (const float*)d_in[12]; const float* pbo = (const float*)d_in[13];
    const float* qW1 = (const float*)d_in[14]; const float* qb1 = (const float*)d_in[15];
    const float* qg1 = (const float*)d_in[16]; const float* qB1 = (const float*)d_in[17];
    const float* qW2 = (const float*)d_in[18]; const float* qb2 = (const float*)d_in[19];
    const float* qg2 = (const float*)d_in[20]; const float* qB2 = (const float*)d_in[21];
    const float* qWo = (const float*)d_in[22]; const float* qbo = (const float*)d_in[23];
    const float* gW  = (const float*)d_in[24]; const float* gb  = (const float*)d_in[25];
    const float* gg  = (const float*)d_in[26]; const float* gB  = (const float*)d_in[27];
    const float* gWz = (const float*)d_in[28]; const float* gbz = (const float*)d_in[29];
    const float* gWc = (const float*)d_in[30]; const float* gbc = (const float*)d_in[31];

    cudaFuncSetAttribute(wm_kernel,
                         cudaFuncAttributeMaxDynamicSharedMemorySize, SMEM_BYTES);

    wm_kernel<<<NBLK, TPB, SMEM_BYTES>>>(tokens, actions, gpost, gprior,
                             pW1, pb1, pg1, pB1, pW2, pb2, pg2, pB2, pWo, pbo,
                             qW1, qb1, qg1, qB1, qW2, qb2, qg2, qB2, qWo, qbo,
                             gW, gb, gg, gB, gWz, gbz, gWc, gbc,
                             (float*)d_out);
}

// round 16
// speedup vs baseline: 2.1595x; 1.0077x over previous
#include <cuda_runtime.h>
#include <cstddef>

// ===========================================================================
// WorldModel RSSM persistent kernel. R=16 full-row GEMM tiles (weights
// loaded exactly once), cp.async smem ring grouped 2x4 stages.
// S=32 C=32 D=4096 H=1024 A=6 B=16 T=64 TOK=4096, out feats [16,64,5120]
// ===========================================================================

#define NBLK 148
#define TPB  512
#define GPB  2                  // 256-thread groups per block
#define NG   (NBLK * GPB)       // 296 groups

#define CH_Q1 64                // prior layer1:  K=4096, Kc=64
#define CH_P1 128               // post  layer1:  K=8192, Kc=64
#define CH_L  32                // layers 2/3:    K=1024, Kc=32
#define CH_ZC 32                // z/cand:        K=5120, Kc=160

// Dynamic smem layout (bytes):
//   [0, 20480)       sA: 2 groups x 2560 floats (A staging; sLN overlays)
//   [20480, 86016)   sW: 2 groups x 8 stages x 256 float4 (weight ring)
#define SMEM_BYTES 86016

// ---------------------------------------------------------------------------
// Device scratch
// ---------------------------------------------------------------------------
__device__ float g_deter[16 * 4096];
__device__ float g_gx[16 * 1024];
__device__ float g_hqA[16 * 1024];
__device__ float g_hqB[16 * 1024];
__device__ float g_hpA[16 * 1024];
__device__ float g_hpB[16 * 1024];
__device__ float g_partQ[CH_Q1 * 16 * 1024];
__device__ float g_partP[CH_P1 * 16 * 1024];
__device__ float g_partZ[CH_ZC * 16 * 4096];
__device__ float g_partC[CH_ZC * 16 * 4096];
__device__ unsigned g_count;
__device__ unsigned g_gen;

// ---------------------------------------------------------------------------
__device__ __forceinline__ float2 ffma2(float2 a, float2 b, float2 c) {
    union U { float2 f; unsigned long long u; };
    U ua, ub, uc, ud;
    ua.f = a; ub.f = b; uc.f = c;
    asm("fma.rn.f32x2 %0, %1, %2, %3;"
        : "=l"(ud.u) : "l"(ua.u), "l"(ub.u), "l"(uc.u));
    return ud.f;
}

__device__ __forceinline__ void cpa16(unsigned saddr, const void* gptr) {
    asm volatile("cp.async.cg.shared.global [%0], [%1], 16;"
                 :: "r"(saddr), "l"(gptr));
}
#define CPA_COMMIT() asm volatile("cp.async.commit_group;" ::: "memory")
#define CPA_WAIT1()  asm volatile("cp.async.wait_group 1;" ::: "memory")

__device__ __forceinline__ void gbar() {
    __syncthreads();
    if (threadIdx.x == 0) {
        volatile unsigned* vg = &g_gen;
        unsigned gen = *vg;
        __threadfence();
        if (atomicAdd(&g_count, 1u) == NBLK - 1) {
            g_count = 0;
            __threadfence();
            *vg = gen + 1;
        } else {
            while (*vg == gen) { __nanosleep(32); }
        }
        __threadfence();
    }
    __syncthreads();
}

// block-wide sum over 512 threads
__device__ __forceinline__ float blockReduceSum(float v, float* sred) {
    int lane = threadIdx.x & 31, wid = threadIdx.x >> 5;
#pragma unroll
    for (int o = 16; o; o >>= 1) v += __shfl_xor_sync(0xffffffffu, v, o);
    __syncthreads();
    if (lane == 0) sred[wid] = v;
    __syncthreads();
    if (wid == 0) {
        float t = (lane < 16) ? sred[lane] : 0.f;
#pragma unroll
        for (int o = 8; o; o >>= 1) t += __shfl_xor_sync(0xffffffffu, t, o);
        if (lane == 0) sred[0] = t;
    }
    __syncthreads();
    return sred[0];
}

struct InDesc { const float* A; int strideA; int offA; int KA; const float* B; };

// 16 rows x 4 cols of FMA for one k slice (sAk = &sA[kk*16]).
// Layout: acc[q*8 + pr*4 + c] holds rows (4q + 2*pr, 4q + 2*pr + 1) in
// (.x, .y) for column c.
__device__ __forceinline__ void fma16(const float* sAk, float4 w, float2* acc) {
    float2 wx = make_float2(w.x, w.x), wy = make_float2(w.y, w.y);
    float2 wz = make_float2(w.z, w.z), ww = make_float2(w.w, w.w);
    const float4* A4 = (const float4*)sAk;
#pragma unroll
    for (int q = 0; q < 4; q++) {
        float4 a = A4[q];
        float2 p0 = make_float2(a.x, a.y), p1 = make_float2(a.z, a.w);
        float2* ac = acc + q * 8;
        ac[0] = ffma2(p0, wx, ac[0]); ac[1] = ffma2(p0, wy, ac[1]);
        ac[2] = ffma2(p0, wz, ac[2]); ac[3] = ffma2(p0, ww, ac[3]);
        ac[4] = ffma2(p1, wx, ac[4]); ac[5] = ffma2(p1, wy, ac[5]);
        ac[6] = ffma2(p1, wz, ac[6]); ac[7] = ffma2(p1, ww, ac[7]);
    }
}

// ---------------------------------------------------------------------------
// GEMM tile: all 16 rows x 1024 cols (256 threads x 4 cols). Weights
// streamed through an 8-stage per-thread smem ring via cp.async.cg,
// grouped 4 stages per commit; barrier-free inner loop.
// Requires Kc % 4 == 0 and Kc >= 8.
// ---------------------------------------------------------------------------
__device__ __forceinline__ void gemm16(
    InDesc in, const float4* __restrict__ W4, int N4,
    int c4base, int k0, int Kc,
    float4* __restrict__ part4, int chunkIdx,
    float* sA, float4* sW, int gtid, int barId)
{
    // stage A[0..15][k0..k0+Kc) -> sA[k*16 + r]
    for (int idx = gtid; idx < 16 * Kc; idx += 256) {
        int k = idx >> 4, r = idx & 15;
        int gk = k0 + k;
        float v = (gk < in.KA) ? in.A[(size_t)r * in.strideA + in.offA + gk]
                               : in.B[(size_t)r * 4096 + (gk - in.KA)];
        sA[idx] = v;
    }
    asm volatile("bar.sync %0, %1;" :: "r"(barId), "r"(256) : "memory");

    float2 acc[32];
#pragma unroll
    for (int i = 0; i < 32; i++) acc[i] = make_float2(0.f, 0.f);

    int col4 = c4base + gtid;
    const float4* Wp = W4 + (size_t)k0 * N4 + col4;
    const size_t step = N4;

    unsigned swaddr = (unsigned)__cvta_generic_to_shared(sW + gtid);

    // prologue: 2 groups of 4 stages
#pragma unroll
    for (int gi = 0; gi < 2; gi++) {
#pragma unroll
        for (int j = 0; j < 4; j++) { cpa16(swaddr + (unsigned)(gi * 4 + j) * 4096u, Wp); Wp += step; }
        CPA_COMMIT();
    }

    for (int kb = 0; kb < Kc; kb += 4) {
        CPA_WAIT1();                                // group for kb retired
#pragma unroll
        for (int j = 0; j < 4; j++) {
            float4 w = sW[((kb + j) & 7) * 256 + gtid];
            fma16(sA + (kb + j) * 16, w, acc);
        }
        if (kb + 8 < Kc) {
#pragma unroll
            for (int j = 0; j < 4; j++) { cpa16(swaddr + (unsigned)((kb + j) & 7) * 4096u, Wp); Wp += step; }
        }
        CPA_COMMIT();                               // keep group count exact
    }

    asm volatile("bar.sync %0, %1;" :: "r"(barId), "r"(256) : "memory");

#pragma unroll
    for (int r = 0; r < 16; r++) {
        const float2* ac = acc + (r >> 2) * 8 + ((r >> 1) & 1) * 4;
        float4 o;
        if (r & 1) o = make_float4(ac[0].y, ac[1].y, ac[2].y, ac[3].y);
        else       o = make_float4(ac[0].x, ac[1].x, ac[2].x, ac[3].x);
        part4[(size_t)(chunkIdx * 16 + r) * N4 + col4] = o;
    }
}

// ---------------------------------------------------------------------------
// Phase: fused layer-1 GEMMs. q: deter@qW1 (K=4096, 64 tiles);
// p: [tok,deter]@pW1 (K=8192, 128 tiles).
// ---------------------------------------------------------------------------
__device__ void phase_g1(bool doq, bool dop, int tp, const float* tokens,
                         const float4* qW1, const float4* pW1,
                         float* sMy, float4* sWMy, int gtid, int gid2, int barId)
{
    int qT = doq ? CH_Q1 : 0;
    int total = qT + (dop ? CH_P1 : 0);
    for (int t = gid2; t < total; t += NG) {
        if (t < qT) {
            InDesc in = { g_deter, 4096, 0, 4096, g_deter };
            gemm16(in, qW1, 256, 0, t * 64, 64,
                   (float4*)g_partQ, t, sMy, sWMy, gtid, barId);
        } else {
            int ch = t - qT;
            InDesc in = { tokens, 64 * 4096, tp * 4096, 4096, g_deter };
            gemm16(in, pW1, 256, 0, ch * 64, 64,
                   (float4*)g_partP, ch, sMy, sWMy, gtid, barId);
        }
    }
}

// ---------------------------------------------------------------------------
// Phase: fused layer-2/3 GEMMs (K=1024, Kc=32, 32 tiles per side).
// ---------------------------------------------------------------------------
__device__ void phase_g23(bool doq, bool dop,
                          const float4* Wq, const float4* Wp,
                          const float* inq, const float* inp,
                          float* sMy, float4* sWMy, int gtid, int gid2, int barId)
{
    int qT = doq ? CH_L : 0;
    int total = qT + (dop ? CH_L : 0);
    for (int t = gid2; t < total; t += NG) {
        bool isq = t < qT;
        int ch = isq ? t : (t - qT);
        InDesc in = { isq ? inq : inp, 1024, 0, 1024, isq ? inq : inp };
        gemm16(in, isq ? Wq : Wp, 256, 0, ch * 32, 32,
               (float4*)(isq ? g_partQ : g_partP), ch, sMy, sWMy, gtid, barId);
    }
}

// ---------------------------------------------------------------------------
// Phase: z/cand GEMM. in=[gx,deter] K=5120, Kc=160, N=4096 each. 256 tiles.
// ---------------------------------------------------------------------------
__device__ void phase_zc(const float4* Wz, const float4* Wc,
                         float* sMy, float4* sWMy, int gtid, int gid2, int barId)
{
    const int total = 2 * 4 * CH_ZC;            // 256
    for (int t = gid2; t < total; t += NG) {
        bool isZ = t < 128;
        int u = t & 127;
        int ch = u >> 2, ct = u & 3;
        InDesc in = { g_gx, 1024, 0, 1024, g_deter };
        gemm16(in, isZ ? Wz : Wc, 1024, ct * 256, ch * 160, 160,
               (float4*)(isZ ? g_partZ : g_partC), ch, sMy, sWMy, gtid, barId);
    }
}

// ---------------------------------------------------------------------------
// Phase: reduce partials + bias + LN + SiLU. Blocks 0..15 q, 16..31 p.
// ---------------------------------------------------------------------------
__device__ void phase_ln(bool doq, bool dop,
                         const float* qb, const float* qg, const float* qB,
                         const float* pb, const float* pg, const float* pB,
                         int chq, int chp, float* outq, float* outp,
                         float4* sLN, float* sred)
{
    int b = blockIdx.x;
    bool active = (b < 32);
    bool isq = b < 16;
    if (active && (isq ? !doq : !dop)) active = false;

    int s = threadIdx.x & 255, qd = threadIdx.x >> 8;
    float4 v = make_float4(0.f, 0.f, 0.f, 0.f);
    if (active) {
        int r = b & 15;
        const float4* part4 = (const float4*)(isq ? g_partQ : g_partP);
        int chunks = isq ? chq : chp;
        for (int ch = qd; ch < chunks; ch += 2) {
            float4 a = part4[(size_t)(ch * 16 + r) * 256 + s];
            v.x += a.x; v.y += a.y; v.z += a.z; v.w += a.w;
        }
    }
    sLN[qd * 256 + s] = v;
    __syncthreads();

    float4 tot = make_float4(0.f, 0.f, 0.f, 0.f);
    float partial = 0.f;
    if (active && qd == 0) {
        float4 a0 = sLN[s], a1 = sLN[256 + s];
        const float4* bias4 = (const float4*)(isq ? qb : pb);
        float4 bb = bias4[s];
        tot.x = a0.x + a1.x + bb.x;
        tot.y = a0.y + a1.y + bb.y;
        tot.z = a0.z + a1.z + bb.z;
        tot.w = a0.w + a1.w + bb.w;
        partial = tot.x + tot.y + tot.z + tot.w;
    }
    float mean = blockReduceSum(partial, sred) * (1.0f / 1024.0f);

    float4 d = make_float4(tot.x - mean, tot.y - mean, tot.z - mean, tot.w - mean);
    float sq = (active && qd == 0) ? (d.x*d.x + d.y*d.y + d.z*d.z + d.w*d.w) : 0.f;
    float var = blockReduceSum(sq, sred) * (1.0f / 1024.0f);

    if (active && qd == 0) {
        int r = b & 15;
        float rstd = rsqrtf(var + 1e-5f);
        const float4* g4 = (const float4*)(isq ? qg : pg);
        const float4* B4 = (const float4*)(isq ? qB : pB);
        float4 gg = g4[s], BB = B4[s], x;
        x.x = d.x * rstd * gg.x + BB.x;
        x.y = d.y * rstd * gg.y + BB.y;
        x.z = d.z * rstd * gg.z + BB.z;
        x.w = d.w * rstd * gg.w + BB.w;
        float4 o;
        o.x = x.x / (1.f + expf(-x.x));
        o.y = x.y / (1.f + expf(-x.y));
        o.z = x.z / (1.f + expf(-x.z));
        o.w = x.w / (1.f + expf(-x.w));
        ((float4*)(isq ? outq : outp))[r * 256 + s] = o;
    }
}

// ---------------------------------------------------------------------------
// Merged sample + GRU-input. 512 threads = 16 warps; each warp handles 2 s.
// Blocks 0..15: prior sample -> out. Blocks 16..31: posterior -> sIdx -> grux.
// ---------------------------------------------------------------------------
__device__ void phase_sample_grux(bool doq, bool dop, int t, int tp,
                                  const float* qbo, const float* pbo,
                                  const float* gprior, const float* gpost,
                                  const float* actions,
                                  const float* gW, const float* gb,
                                  const float* gg, const float* gB,
                                  int* sIdx, float* sAct, float* sred,
                                  float* out)
{
    int b = blockIdx.x;
    bool isq = b < 16;
    bool samp = (b < 32) && (isq ? doq : dop);
    bool grux = (b >= 16) && (b < 32) && dop;
    int r = b & 15;
    int wid = threadIdx.x >> 5, lane = threadIdx.x & 31;

    if (grux && threadIdx.x < 6)
        sAct[threadIdx.x] = actions[((size_t)r * 64 + tp) * 6 + threadIdx.x];

    if (samp) {
#pragma unroll
        for (int half = 0; half < 2; half++) {
            int s = wid + half * 16;
            int col = s * 32 + lane;
            const float* part = isq ? g_partQ : g_partP;
            float logit = (isq ? qbo : pbo)[col];
#pragma unroll
            for (int ch = 0; ch < CH_L; ch++)
                logit += part[(size_t)(ch * 16 + r) * 1024 + col];

            float mx = logit;
#pragma unroll
            for (int o = 16; o; o >>= 1) mx = fmaxf(mx, __shfl_xor_sync(0xffffffffu, mx, o));
            float e = expf(logit - mx);
            float se = e;
#pragma unroll
            for (int o = 16; o; o >>= 1) se += __shfl_xor_sync(0xffffffffu, se, o);
            float p = 0.99f * (e / se) + (0.01f / 32.0f);

            int tt = isq ? t : tp;
            const float* gum = isq ? gprior : gpost;
            float score = logf(p) + gum[(size_t)((tt * 16 + r) * 32 + s) * 32 + lane];

            float bs = score; int bi = lane;
#pragma unroll
            for (int o = 16; o; o >>= 1) {
                float os = __shfl_xor_sync(0xffffffffu, bs, o);
                int   oi = __shfl_xor_sync(0xffffffffu, bi, o);
                if (os > bs || (os == bs && oi < bi)) { bs = os; bi = oi; }
            }
            if (isq) {
                out[((size_t)r * 64 + t) * 5120 + 4096 + col] = (lane == bi) ? 1.0f : 0.0f;
            } else if (lane == bi) {
                sIdx[s] = bi;
            }
        }
    }
    __syncthreads();

    float v[2] = {0.f, 0.f};
    if (grux) {
#pragma unroll
        for (int ci = 0; ci < 2; ci++) {
            int col = threadIdx.x + ci * 512;
            float a = gb[col];
#pragma unroll
            for (int s2 = 0; s2 < 32; s2++)
                a += gW[(size_t)(s2 * 32 + sIdx[s2]) * 1024 + col];
#pragma unroll
            for (int j = 0; j < 6; j++)
                a += sAct[j] * gW[(size_t)(1024 + j) * 1024 + col];
            v[ci] = a;
        }
    }
    float mean = blockReduceSum(grux ? (v[0] + v[1]) : 0.f, sred) * (1.0f / 1024.0f);
    float d0 = v[0] - mean, d1 = v[1] - mean;
    float var = blockReduceSum(grux ? (d0 * d0 + d1 * d1) : 0.f, sred) * (1.0f / 1024.0f);
    if (grux) {
        float rstd = rsqrtf(var + 1e-5f);
#pragma unroll
        for (int ci = 0; ci < 2; ci++) {
            int col = threadIdx.x + ci * 512;
            float d = (ci ? d1 : d0);
            float x = d * rstd * gg[col] + gB[col];
            g_gx[r * 1024 + col] = x / (1.0f + expf(-x));
        }
    }
}

// ---------------------------------------------------------------------------
// Phase: gate — reduce z/cand partials (4-lane split), update deter, write out.
// ---------------------------------------------------------------------------
__device__ void phase_gate(int t, const float* gbz, const float* gbc,
                           float* out)
{
    int gt = blockIdx.x * TPB + threadIdx.x;    // 75776 threads
    int q4 = gt & 3, slot = gt >> 2;            // 16384 float4 slots
    if (slot >= 16384) return;
    int b = slot >> 10, c4 = slot & 1023;

    const float4* pz4 = (const float4*)g_partZ;
    const float4* pc4 = (const float4*)g_partC;
    float4 zp = make_float4(0.f, 0.f, 0.f, 0.f);
    float4 cp = make_float4(0.f, 0.f, 0.f, 0.f);
#pragma unroll
    for (int ch = q4; ch < CH_ZC; ch += 4) {
        float4 a = pz4[(size_t)(ch * 16 + b) * 1024 + c4];
        float4 c = pc4[(size_t)(ch * 16 + b) * 1024 + c4];
        zp.x += a.x; zp.y += a.y; zp.z += a.z; zp.w += a.w;
        cp.x += c.x; cp.y += c.y; cp.z += c.z; cp.w += c.w;
    }
#pragma unroll
    for (int off = 2; off; off >>= 1) {
        zp.x += __shfl_down_sync(0xffffffffu, zp.x, off);
        zp.y += __shfl_down_sync(0xffffffffu, zp.y, off);
        zp.z += __shfl_down_sync(0xffffffffu, zp.z, off);
        zp.w += __shfl_down_sync(0xffffffffu, zp.w, off);
        cp.x += __shfl_down_sync(0xffffffffu, cp.x, off);
        cp.y += __shfl_down_sync(0xffffffffu, cp.y, off);
        cp.z += __shfl_down_sync(0xffffffffu, cp.z, off);
        cp.w += __shfl_down_sync(0xffffffffu, cp.w, off);
    }
    if (q4 == 0) {
        float4 bz = ((const float4*)gbz)[c4], bc = ((const float4*)gbc)[c4];
        zp.x += bz.x; zp.y += bz.y; zp.z += bz.z; zp.w += bz.w;
        cp.x += bc.x; cp.y += bc.y; cp.z += bc.z; cp.w += bc.w;
        float4* dt4 = (float4*)g_deter;
        float4 dv = dt4[b * 1024 + c4], dn;
        float z, cd;
        z = 1.f / (1.f + expf(-zp.x)); cd = tanhf(cp.x); dn.x = (1.f - z) * dv.x + z * cd;
        z = 1.f / (1.f + expf(-zp.y)); cd = tanhf(cp.y); dn.y = (1.f - z) * dv.y + z * cd;
        z = 1.f / (1.f + expf(-zp.z)); cd = tanhf(cp.z); dn.z = (1.f - z) * dv.z + z * cd;
        z = 1.f / (1.f + expf(-zp.w)); cd = tanhf(cp.w); dn.w = (1.f - z) * dv.w + z * cd;
        dt4[b * 1024 + c4] = dn;
        ((float4*)(out + ((size_t)b * 64 + t) * 5120))[c4] = dn;
    }
}

// ---------------------------------------------------------------------------
__global__ void __launch_bounds__(TPB, 1)
wm_kernel(const float* tokens, const float* actions,
          const float* gpost, const float* gprior,
          const float* pW1, const float* pb1, const float* pg1, const float* pB1,
          const float* pW2, const float* pb2, const float* pg2, const float* pB2,
          const float* pWo, const float* pbo,
          const float* qW1, const float* qb1, const float* qg1, const float* qB1,
          const float* qW2, const float* qb2, const float* qg2, const float* qB2,
          const float* qWo, const float* qbo,
          const float* gW, const float* gb, const float* gg, const float* gB,
          const float* gWz, const float* gbz, const float* gWc, const float* gbc,
          float* out)
{
    extern __shared__ char dynsmem[];
    float*  sA_all = (float*)dynsmem;                       // 2 x 2560 floats
    float4* sW_all = (float4*)(dynsmem + 20480);            // 2 x 2048 float4
    float4* sLN    = (float4*)dynsmem;                      // overlay (LN only)
    __shared__ float sRed[16];
    __shared__ int   sIdx[32];
    __shared__ float sAct[6];

    int tid = threadIdx.x;
    int g = tid >> 8, gtid = tid & 255;
    int gid2 = g * NBLK + blockIdx.x;
    float*  sMy  = sA_all + g * 2560;
    float4* sWMy = sW_all + g * 2048;
    int barId = g + 1;

    const float4* pW1v = (const float4*)pW1; const float4* pW2v = (const float4*)pW2;
    const float4* pWov = (const float4*)pWo;
    const float4* qW1v = (const float4*)qW1; const float4* qW2v = (const float4*)qW2;
    const float4* qWov = (const float4*)qWo;
    const float4* gWzv = (const float4*)gWz; const float4* gWcv = (const float4*)gWc;

    for (int i = blockIdx.x * TPB + tid; i < 16 * 4096; i += NBLK * TPB)
        g_deter[i] = 0.0f;
    gbar();

    // prologue: posterior(0) + grux(0)
    phase_g1(false, true, 0, tokens, qW1v, pW1v, sMy, sWMy, gtid, gid2, barId);   gbar();
    phase_ln(false, true, qb1, qg1, qB1, pb1, pg1, pB1, CH_Q1, CH_P1,
             g_hqA, g_hpA, sLN, sRed);                                            gbar();
    phase_g23(false, true, qW2v, pW2v, g_hqA, g_hpA, sMy, sWMy, gtid, gid2, barId); gbar();
    phase_ln(false, true, qb2, qg2, qB2, pb2, pg2, pB2, CH_L, CH_L,
             g_hqB, g_hpB, sLN, sRed);                                            gbar();
    phase_g23(false, true, qWov, pWov, g_hqB, g_hpB, sMy, sWMy, gtid, gid2, barId); gbar();
    phase_sample_grux(false, true, 0, 0, qbo, pbo, gprior, gpost,
                      actions, gW, gb, gg, gB, sIdx, sAct, sRed, out);            gbar();

    for (int t = 0; t < 64; t++) {
        phase_zc(gWzv, gWcv, sMy, sWMy, gtid, gid2, barId);                       gbar();
        phase_gate(t, gbz, gbc, out);                                             gbar();

        bool dop = (t < 63);
        phase_g1(true, dop, t + 1, tokens, qW1v, pW1v, sMy, sWMy, gtid, gid2, barId); gbar();
        phase_ln(true, dop, qb1, qg1, qB1, pb1, pg1, pB1, CH_Q1, CH_P1,
                 g_hqA, g_hpA, sLN, sRed);                                            gbar();
        phase_g23(true, dop, qW2v, pW2v, g_hqA, g_hpA, sMy, sWMy, gtid, gid2, barId); gbar();
        phase_ln(true, dop, qb2, qg2, qB2, pb2, pg2, pB2, CH_L, CH_L,
                 g_hqB, g_hpB, sLN, sRed);                                            gbar();
        phase_g23(true, dop, qWov, pWov, g_hqB, g_hpB, sMy, sWMy, gtid, gid2, barId); gbar();
        phase_sample_grux(true, dop, t, t + 1, qbo, pbo, gprior, gpost,
                          actions, gW, gb, gg, gB, sIdx, sAct, sRed, out);            gbar();
    }
}

// ---------------------------------------------------------------------------
extern "C" void kernel_launch(void* const* d_in, const int* in_sizes, int n_in,
                              void* d_out, int out_size) {
    const float* tokens  = (const float*)d_in[0];
    const float* actions = (const float*)d_in[1];
    const float* gpost   = (const float*)d_in[2];
    const float* gprior  = (const float*)d_in[3];
    const float* pW1 = (const float*)d_in[4];  const float* pb1 = (const float*)d_in[5];
    const float* pg1 = (const float*)d_in[6];  const float* pB1 = (const float*)d_in[7];
    const float* pW2 = (const float*)d_in[8];  const float* pb2 = (const float*)d_in[9];
    const float* pg2 = (const float*)d_in[10]; const float* pB2 = (const float*)d_in[11];
    const float* pWo = (const float*)d_in[12]; const float* pbo = (const float*)d_in[13];
    const float* qW1 = (const float*)d_in[14]; const float* qb1 = (const float*)d_in[15];
    const float* qg1 = (const float*)d_in[16]; const float* qB1 = (const float*)d_in[17];
    const float* qW2 = (const float*)d_in[18]; const float* qb2 = (const float*)d_in[19];
    const float* qg2 = (const float*)d_in[20]; const float* qB2 = (const float*)d_in[21];
    const float* qWo = (const float*)d_in[22]; const float* qbo = (const float*)d_in[23];
    const float* gW  = (const float*)d_in[24]; const float* gb  = (const float*)d_in[25];
    const float* gg  = (const float*)d_in[26]; const float* gB  = (const float*)d_in[27];
    const float* gWz = (const float*)d_in[28]; const float* gbz = (const float*)d_in[29];
    const float* gWc = (const float*)d_in[30]; const float* gbc = (const float*)d_in[31];

    cudaFuncSetAttribute(wm_kernel,
                         cudaFuncAttributeMaxDynamicSharedMemorySize, SMEM_BYTES);

    wm_kernel<<<NBLK, TPB, SMEM_BYTES>>>(tokens, actions, gpost, gprior,
                             pW1, pb1, pg1, pB1, pW2, pb2, pg2, pB2, pWo, pbo,
                             qW1, qb1, qg1, qB1, qW2, qb2, qg2, qB2, qWo, qbo,
                             gW, gb, gg, gB, gWz, gbz, gWc, gbc,
                             (float*)d_out);
}